// round 1
// baseline (speedup 1.0000x reference)
#include <cuda_runtime.h>

// Problem constants
constexpr int B_ = 8, L_ = 12, C_ = 4096, O_ = 128, N_ = 4224;
constexpr int E_ = 64, A_ = 64, H_ = 256;

// ---------------- scratch (device globals; no allocation allowed) ----------
__device__ __align__(16) float g_objIn[B_ * O_ * E_];
__device__ __align__(16) float g_objOut[B_ * O_ * E_];
__device__ __align__(16) float g_T1c[C_ * H_];        // thoughtOut(concepts) @ W1_t
__device__ __align__(16) float g_T1o[B_ * O_ * H_];   // thoughtOut(objects)  @ W1_t
__device__ __align__(16) float g_meta[B_ * L_ * A_];  // post-update meta at step t
__device__ __align__(16) float g_u[B_ * L_ * H_];     // meta @ W1_m + b1
__device__ __align__(16) float g_arg[B_ * L_ * E_];   // concept_embOut[program_args]
__device__ __align__(16) float g_att[B_ * N_ * A_];   // attention state
__device__ __align__(16) float g_GT[B_ * A_ * H_];    // G transposed: [a][h]
__device__ __align__(16) float g_attsum[B_ * A_];
__device__ __align__(16) float g_M[B_ * E_ * A_];     // 64x64 transfer matrix

// ---------------- precompute kernels ---------------------------------------

// object embeddings (class + sum of 8 attrs), In and Out
__global__ void k_obj(const float* __restrict__ clsIn, const float* __restrict__ clsOut,
                      const float* __restrict__ atIn, const float* __restrict__ atOut,
                      const int* __restrict__ gt_cls, const int* __restrict__ gt_attr) {
    int e = threadIdx.x;              // 0..63
    int o = blockIdx.x * 4 + threadIdx.y;
    int b = blockIdx.y;
    int cls = gt_cls[b * O_ + o];
    float vi = clsIn[cls * E_ + e];
    float vo = clsOut[cls * E_ + e];
#pragma unroll
    for (int k = 0; k < 8; k++) {
        int at = gt_attr[(b * O_ + o) * 8 + k];
        vi += atIn[at * E_ + e];
        vo += atOut[at * E_ + e];
    }
    g_objIn[(b * O_ + o) * E_ + e] = vi;
    g_objOut[(b * O_ + o) * E_ + e] = vo;
}

// T1c[n,h] = concept_embOut[n,:] @ axon_w1[0:64,:]
__global__ void __launch_bounds__(256) k_T1c(const float* __restrict__ cOut,
                                             const float* __restrict__ w1) {
    int h = threadIdx.x;
    int n0 = blockIdx.x * 8;
    __shared__ float s_emb[512];
    for (int i = h; i < 512; i += 256) s_emb[i] = cOut[n0 * E_ + i];
    __syncthreads();
    float acc[8];
#pragma unroll
    for (int r = 0; r < 8; r++) acc[r] = 0.f;
    for (int e = 0; e < 64; e++) {
        float w = __ldg(&w1[e * H_ + h]);
#pragma unroll
        for (int r = 0; r < 8; r++) acc[r] += s_emb[r * 64 + e] * w;
    }
#pragma unroll
    for (int r = 0; r < 8; r++) g_T1c[(n0 + r) * H_ + h] = acc[r];
}

// T1o[b,o,h] = objOut[b,o,:] @ axon_w1[0:64,:]
__global__ void __launch_bounds__(256) k_T1o(const float* __restrict__ w1) {
    int h = threadIdx.x;
    int b = blockIdx.y;
    int o0 = blockIdx.x * 8;
    __shared__ float s_emb[512];
    for (int i = h; i < 512; i += 256) s_emb[i] = g_objOut[(b * O_ + o0) * E_ + i];
    __syncthreads();
    float acc[8];
#pragma unroll
    for (int r = 0; r < 8; r++) acc[r] = 0.f;
    for (int e = 0; e < 64; e++) {
        float w = __ldg(&w1[e * H_ + h]);
#pragma unroll
        for (int r = 0; r < 8; r++) acc[r] += s_emb[r * 64 + e] * w;
    }
#pragma unroll
    for (int r = 0; r < 8; r++) g_T1o[(b * O_ + o0 + r) * H_ + h] = acc[r];
}

// meta recurrence for all 12 steps + u + arg gather (tiny, one block per batch)
__global__ void __launch_bounds__(256) k_meta(
    const float* __restrict__ meta_init, const float* __restrict__ cOut,
    const float* __restrict__ mw1, const float* __restrict__ mb1,
    const float* __restrict__ mw2, const float* __restrict__ mb2,
    const float* __restrict__ aw1, const float* __restrict__ ab1,
    const int* __restrict__ ops, const int* __restrict__ args) {
    int b = blockIdx.x;
    int tid = threadIdx.x;
    __shared__ float s_meta[64], s_arg[64], s_h[256];
    if (tid < 64) s_meta[tid] = meta_init[tid];
    __syncthreads();
    for (int t = 0; t < L_; t++) {
        if (tid < 64) {
            int ai = args[b * L_ + t];
            float v = cOut[ai * E_ + tid];
            s_arg[tid] = v;
            g_arg[(b * L_ + t) * E_ + tid] = v;
        }
        __syncthreads();
        float pre = mb1[tid];
#pragma unroll
        for (int a = 0; a < 64; a++) pre += s_meta[a] * __ldg(&mw1[a * H_ + tid]);
#pragma unroll
        for (int e = 0; e < 64; e++) pre += s_arg[e] * __ldg(&mw1[(64 + e) * H_ + tid]);
        s_h[tid] = fmaxf(pre, 0.f);
        __syncthreads();
        if (tid < 64) {
            float nm = mb2[tid];
            for (int hh = 0; hh < 256; hh++) nm += s_h[hh] * __ldg(&mw2[hh * A_ + tid]);
            float nv = (ops[b * L_ + t] == 0) ? nm : s_meta[tid];
            s_meta[tid] = nv;
            g_meta[(b * L_ + t) * A_ + tid] = nv;
        }
        __syncthreads();
        float uv = ab1[tid];
#pragma unroll
        for (int a = 0; a < 64; a++) uv += s_meta[a] * __ldg(&aw1[(64 + a) * H_ + tid]);
        g_u[(b * L_ + t) * H_ + tid] = uv;
        __syncthreads();
    }
}

__global__ void k_attinit(const float* __restrict__ att_init) {
    int i = blockIdx.x * 256 + threadIdx.x;
    if (i < B_ * N_ * A_) g_att[i] = att_init[i & 63];
}

// ---------------- per-step kernels ------------------------------------------

__global__ void k_zero() {
    int i = blockIdx.x * 256 + threadIdx.x;
    if (i < B_ * A_ * H_) g_GT[i] = 0.f;
    if (i < B_ * A_) g_attsum[i] = 0.f;
    if (i < B_ * E_ * A_) g_M[i] = 0.f;
}

// K1: G[h,a] += relu(T1[n,h]+u[h]) * att[n,a]  over 64-row chunk (transfer only)
__global__ void __launch_bounds__(256) k_G(const int* __restrict__ ops, int t) {
    int b = blockIdx.y;
    if (ops[b * L_ + t] != 2) return;
    int tid = threadIdx.x;  // h
    float uh = g_u[(b * L_ + t) * H_ + tid];
    __shared__ __align__(16) float4 s_att[256];  // 16 rows x 16 float4
    float acc[64];
#pragma unroll
    for (int i = 0; i < 64; i++) acc[i] = 0.f;
    float as0 = 0.f, as1 = 0.f, as2 = 0.f, as3 = 0.f;
    int nbase = blockIdx.x * 64;
    const float4* gatt4 = reinterpret_cast<const float4*>(g_att);
    for (int tile = 0; tile < 4; ++tile) {
        int n0 = nbase + tile * 16;
        float4 v = gatt4[(size_t)(b * N_ + n0) * 16 + tid];
        s_att[tid] = v;
        as0 += v.x; as1 += v.y; as2 += v.z; as3 += v.w;
        __syncthreads();
        for (int nl = 0; nl < 16; ++nl) {
            int n = n0 + nl;
            float t1 = (n < C_) ? g_T1c[n * H_ + tid]
                                : g_T1o[(b * O_ + (n - C_)) * H_ + tid];
            float hv = fmaxf(t1 + uh, 0.f);
#pragma unroll
            for (int i = 0; i < 16; i++) {
                float4 w = s_att[nl * 16 + i];
                acc[4 * i + 0] += hv * w.x;
                acc[4 * i + 1] += hv * w.y;
                acc[4 * i + 2] += hv * w.z;
                acc[4 * i + 3] += hv * w.w;
            }
        }
        __syncthreads();
    }
    // transposed G => coalesced atomics (lane index = h)
#pragma unroll
    for (int a = 0; a < 64; a++)
        atomicAdd(&g_GT[(b * A_ + a) * H_ + tid], acc[a]);
    int a0 = (tid & 15) * 4;
    atomicAdd(&g_attsum[b * A_ + a0 + 0], as0);
    atomicAdd(&g_attsum[b * A_ + a0 + 1], as1);
    atomicAdd(&g_attsum[b * A_ + a0 + 2], as2);
    atomicAdd(&g_attsum[b * A_ + a0 + 3], as3);
}

// K2: M[e,a] = (W2^T G + b2 (x) attsum) / N   — partial over 16-h chunks
__global__ void __launch_bounds__(256) k_M(const int* __restrict__ ops, int t,
                                           const float* __restrict__ w2,
                                           const float* __restrict__ b2) {
    int b = blockIdx.y;
    if (ops[b * L_ + t] != 2) return;
    int h0 = blockIdx.x * 16;
    int tid = threadIdx.x;
    __shared__ float s_G[64][17];   // [a][lh], padded
    __shared__ float s_w2[16 * 64]; // [lh][e]
    for (int i = tid; i < 1024; i += 256) {
        int lh = i & 15, a = i >> 4;
        s_G[a][lh] = g_GT[(b * A_ + a) * H_ + h0 + lh];
    }
    for (int i = tid; i < 1024; i += 256) {
        int lh = i >> 6, e = i & 63;
        s_w2[lh * 64 + e] = w2[(h0 + lh) * A_ + e];  // w2 is (H,E)
    }
    __syncthreads();
    int a = tid & 63;
    int eg = tid >> 6;  // 0..3 -> e range eg*16..+15
    float acc[16];
#pragma unroll
    for (int j = 0; j < 16; j++) acc[j] = 0.f;
    for (int lh = 0; lh < 16; lh++) {
        float gv = s_G[a][lh];
#pragma unroll
        for (int j = 0; j < 16; j++) acc[j] += s_w2[lh * 64 + eg * 16 + j] * gv;
    }
    const float invN = 1.0f / (float)N_;
    if (blockIdx.x == 0) {
        float asum = g_attsum[b * A_ + a];
#pragma unroll
        for (int j = 0; j < 16; j++) acc[j] += b2[eg * 16 + j] * asum;
    }
#pragma unroll
    for (int j = 0; j < 16; j++)
        atomicAdd(&g_M[(b * E_ + eg * 16 + j) * A_ + a], acc[j] * invN);
}

// K3: attention update (insert or transfer); 32 rows per block
__global__ void __launch_bounds__(512) k_upd(const int* __restrict__ ops, int t,
                                             const float* __restrict__ cIn,
                                             const float* __restrict__ cOut) {
    int b = blockIdx.y;
    int op = ops[b * L_ + t];
    if (op == 0) return;
    int tx = threadIdx.x, ty = threadIdx.y;
    int tid = ty * 64 + tx;
    int n0 = blockIdx.x * 32;
    __shared__ __align__(16) float s_M[4096];
    __shared__ __align__(16) float s_row[2048];
    __shared__ __align__(16) float s_arg[64];
    if (op == 2) {
        float4* d = (float4*)s_M;
        const float4* s = (const float4*)(&g_M[b * 4096]);
        d[tid] = s[tid];
        d[tid + 512] = s[tid + 512];
        int r = tid >> 4, c = tid & 15, n = n0 + r;
        const float4* src = (n < C_)
            ? ((const float4*)cIn) + (size_t)n * 16
            : ((const float4*)g_objIn) + (size_t)(b * O_ + n - C_) * 16;
        ((float4*)s_row)[tid] = src[c];
    } else {
        int r = tid >> 4, c = tid & 15, n = n0 + r;
        const float4* src = (n < C_)
            ? ((const float4*)cOut) + (size_t)n * 16
            : ((const float4*)g_objOut) + (size_t)(b * O_ + n - C_) * 16;
        ((float4*)s_row)[tid] = src[c];
        if (tid < 64) s_arg[tid] = g_arg[(b * L_ + t) * E_ + tid];
    }
    __syncthreads();
    int a = tx;
    int rbase = ty * 4;
    float delta[4];
    if (op == 2) {
        float d0 = 0.f, d1 = 0.f, d2 = 0.f, d3 = 0.f;
#pragma unroll
        for (int e4 = 0; e4 < 16; e4++) {
            float m0 = s_M[(e4 * 4 + 0) * 64 + a];
            float m1 = s_M[(e4 * 4 + 1) * 64 + a];
            float m2 = s_M[(e4 * 4 + 2) * 64 + a];
            float m3 = s_M[(e4 * 4 + 3) * 64 + a];
            float4 v0 = ((float4*)s_row)[(rbase + 0) * 16 + e4];
            float4 v1 = ((float4*)s_row)[(rbase + 1) * 16 + e4];
            float4 v2 = ((float4*)s_row)[(rbase + 2) * 16 + e4];
            float4 v3 = ((float4*)s_row)[(rbase + 3) * 16 + e4];
            d0 += v0.x * m0 + v0.y * m1 + v0.z * m2 + v0.w * m3;
            d1 += v1.x * m0 + v1.y * m1 + v1.z * m2 + v1.w * m3;
            d2 += v2.x * m0 + v2.y * m1 + v2.z * m2 + v2.w * m3;
            d3 += v3.x * m0 + v3.y * m1 + v3.z * m2 + v3.w * m3;
        }
        delta[0] = d0; delta[1] = d1; delta[2] = d2; delta[3] = d3;
    } else {
        float metaA = g_meta[(b * L_ + t) * A_ + a];
#pragma unroll
        for (int r = 0; r < 4; r++) {
            float p = 0.f;
#pragma unroll
            for (int e4 = 0; e4 < 16; e4++) {
                float4 av = ((float4*)s_arg)[e4];
                float4 tv = ((float4*)s_row)[(rbase + r) * 16 + e4];
                p += av.x * tv.x + av.y * tv.y + av.z * tv.z + av.w * tv.w;
            }
            delta[r] = metaA * p * (1.0f / 64.0f);
        }
    }
#pragma unroll
    for (int r = 0; r < 4; r++) {
        size_t idx = ((size_t)(b * N_ + n0 + rbase + r)) * A_ + a;
        g_att[idx] += delta[r];
    }
}

// ---------------- epilogue: mean(att^2) + log_softmax ------------------------
__global__ void __launch_bounds__(1024) k_soft(float* __restrict__ out) {
    int b = blockIdx.x;
    int tid = threadIdx.x;
    __shared__ float s_ol[N_];
    __shared__ float s_red[1024];
    float lmax = -1e30f;
    for (int n = tid; n < N_; n += 1024) {
        const float4* row = (const float4*)&g_att[(size_t)(b * N_ + n) * A_];
        float s = 0.f;
#pragma unroll
        for (int i = 0; i < 16; i++) {
            float4 v = row[i];
            s += v.x * v.x + v.y * v.y + v.z * v.z + v.w * v.w;
        }
        s *= (1.0f / 64.0f);
        s_ol[n] = s;
        lmax = fmaxf(lmax, s);
    }
    s_red[tid] = lmax;
    __syncthreads();
    for (int s = 512; s > 0; s >>= 1) {
        if (tid < s) s_red[tid] = fmaxf(s_red[tid], s_red[tid + s]);
        __syncthreads();
    }
    float mx = s_red[0];
    __syncthreads();
    float lsum = 0.f;
    for (int n = tid; n < N_; n += 1024) lsum += expf(s_ol[n] - mx);
    s_red[tid] = lsum;
    __syncthreads();
    for (int s = 512; s > 0; s >>= 1) {
        if (tid < s) s_red[tid] += s_red[tid + s];
        __syncthreads();
    }
    float lse = logf(s_red[0]) + mx;
    for (int n = tid; n < N_; n += 1024) out[b * N_ + n] = s_ol[n] - lse;
}

// ---------------- launch ------------------------------------------------------
extern "C" void kernel_launch(void* const* d_in, const int* in_sizes, int n_in,
                              void* d_out, int out_size) {
    const float* class_embIn   = (const float*)d_in[0];
    const float* class_embOut  = (const float*)d_in[1];
    const float* attr_embIn    = (const float*)d_in[2];
    const float* attr_embOut   = (const float*)d_in[3];
    const float* concept_embIn = (const float*)d_in[4];
    const float* concept_embOut= (const float*)d_in[5];
    const float* meta_init     = (const float*)d_in[6];
    // d_in[7] = object_init (unused by the reference)
    const float* attention_init= (const float*)d_in[8];
    const float* axon_w1       = (const float*)d_in[9];
    const float* axon_b1       = (const float*)d_in[10];
    const float* axon_w2       = (const float*)d_in[11];
    const float* axon_b2       = (const float*)d_in[12];
    const float* meta_w1       = (const float*)d_in[13];
    const float* meta_b1       = (const float*)d_in[14];
    const float* meta_w2       = (const float*)d_in[15];
    const float* meta_b2       = (const float*)d_in[16];
    const int*   program_ops   = (const int*)d_in[17];
    const int*   program_args  = (const int*)d_in[18];
    const int*   gt_classes    = (const int*)d_in[19];
    const int*   gt_attributes = (const int*)d_in[20];
    float* out = (float*)d_out;

    k_obj<<<dim3(32, B_), dim3(64, 4)>>>(class_embIn, class_embOut, attr_embIn,
                                         attr_embOut, gt_classes, gt_attributes);
    k_T1c<<<C_ / 8, 256>>>(concept_embOut, axon_w1);
    k_T1o<<<dim3(O_ / 8, B_), 256>>>(axon_w1);
    k_meta<<<B_, 256>>>(meta_init, concept_embOut, meta_w1, meta_b1, meta_w2,
                        meta_b2, axon_w1, axon_b1, program_ops, program_args);
    k_attinit<<<(B_ * N_ * A_ + 255) / 256, 256>>>(attention_init);

    for (int t = 0; t < L_; t++) {
        k_zero<<<(B_ * A_ * H_ + 255) / 256, 256>>>();
        k_G<<<dim3(N_ / 64, B_), 256>>>(program_ops, t);
        k_M<<<dim3(H_ / 16, B_), 256>>>(program_ops, t, axon_w2, axon_b2);
        k_upd<<<dim3(N_ / 32, B_), dim3(64, 8)>>>(program_ops, t, concept_embIn,
                                                  concept_embOut);
    }
    k_soft<<<B_, 1024>>>(out);
}

// round 2
// speedup vs baseline: 1.3698x; 1.3698x over previous
#include <cuda_runtime.h>

// Problem constants
constexpr int B_ = 8, L_ = 12, C_ = 4096, O_ = 128, N_ = 4224;
constexpr int E_ = 64, A_ = 64, H_ = 256;

// ---------------- scratch (device globals; no allocation allowed) ----------
__device__ __align__(16) float g_objIn[B_ * O_ * E_];
__device__ __align__(16) float g_objOut[B_ * O_ * E_];
__device__ __align__(16) float g_T1c[C_ * H_];        // thoughtOut(concepts) @ W1_t
__device__ __align__(16) float g_T1o[B_ * O_ * H_];   // thoughtOut(objects)  @ W1_t
__device__ __align__(16) float g_meta[B_ * L_ * A_];  // post-update meta at step t
__device__ __align__(16) float g_u[B_ * L_ * H_];     // meta @ W1_m(axon) + b1
__device__ __align__(16) float g_arg[B_ * L_ * E_];   // concept_embOut[program_args]
__device__ __align__(16) float g_att[B_ * N_ * A_];   // attention state
__device__ __align__(16) float g_GT[B_ * A_ * H_];    // G transposed: [a][h]
__device__ __align__(16) float g_attsum[B_ * A_];
__device__ __align__(16) float g_M[B_ * E_ * A_];     // 64x64 transfer matrix
__device__ __align__(16) float g_ol[B_ * N_];         // output_length
__device__ int g_olmax[B_];                            // float-as-int max (ol >= 0)

// ---------------- precompute kernels ---------------------------------------

__global__ void k_obj(const float* __restrict__ clsIn, const float* __restrict__ clsOut,
                      const float* __restrict__ atIn, const float* __restrict__ atOut,
                      const int* __restrict__ gt_cls, const int* __restrict__ gt_attr) {
    int e = threadIdx.x;              // 0..63
    int o = blockIdx.x * 4 + threadIdx.y;
    int b = blockIdx.y;
    int cls = gt_cls[b * O_ + o];
    float vi = clsIn[cls * E_ + e];
    float vo = clsOut[cls * E_ + e];
#pragma unroll
    for (int k = 0; k < 8; k++) {
        int at = gt_attr[(b * O_ + o) * 8 + k];
        vi += atIn[at * E_ + e];
        vo += atOut[at * E_ + e];
    }
    g_objIn[(b * O_ + o) * E_ + e] = vi;
    g_objOut[(b * O_ + o) * E_ + e] = vo;
}

// T1c[n,h] = concept_embOut[n,:] @ axon_w1[0:64,:]
__global__ void __launch_bounds__(256) k_T1c(const float* __restrict__ cOut,
                                             const float* __restrict__ w1) {
    int h = threadIdx.x;
    int n0 = blockIdx.x * 8;
    __shared__ float s_emb[512];
    for (int i = h; i < 512; i += 256) s_emb[i] = cOut[n0 * E_ + i];
    __syncthreads();
    float acc[8];
#pragma unroll
    for (int r = 0; r < 8; r++) acc[r] = 0.f;
    for (int e = 0; e < 64; e++) {
        float w = __ldg(&w1[e * H_ + h]);
#pragma unroll
        for (int r = 0; r < 8; r++) acc[r] += s_emb[r * 64 + e] * w;
    }
#pragma unroll
    for (int r = 0; r < 8; r++) g_T1c[(n0 + r) * H_ + h] = acc[r];
}

// T1o[b,o,h] = objOut[b,o,:] @ axon_w1[0:64,:]
__global__ void __launch_bounds__(256) k_T1o(const float* __restrict__ w1) {
    int h = threadIdx.x;
    int b = blockIdx.y;
    int o0 = blockIdx.x * 8;
    __shared__ float s_emb[512];
    for (int i = h; i < 512; i += 256) s_emb[i] = g_objOut[(b * O_ + o0) * E_ + i];
    __syncthreads();
    float acc[8];
#pragma unroll
    for (int r = 0; r < 8; r++) acc[r] = 0.f;
    for (int e = 0; e < 64; e++) {
        float w = __ldg(&w1[e * H_ + h]);
#pragma unroll
        for (int r = 0; r < 8; r++) acc[r] += s_emb[r * 64 + e] * w;
    }
#pragma unroll
    for (int r = 0; r < 8; r++) g_T1o[(b * O_ + o0 + r) * H_ + h] = acc[r];
}

// meta recurrence for all 12 steps (weights cached in smem); u moved to k_u.
__global__ void __launch_bounds__(256) k_meta(
    const float* __restrict__ meta_init, const float* __restrict__ cOut,
    const float* __restrict__ mw1, const float* __restrict__ mb1,
    const float* __restrict__ mw2, const float* __restrict__ mb2,
    const int* __restrict__ ops, const int* __restrict__ args) {
    extern __shared__ float dsm[];
    float* s_mw1 = dsm;               // 128*256 floats (128 KB)
    float* s_mw2 = dsm + 128 * 256;   // 256*64 floats  (64 KB)
    __shared__ float s_meta[64], s_arg[64], s_h[256], s_part[256];
    int b = blockIdx.x;
    int tid = threadIdx.x;

    // stage weights in smem (once)
    {
        const float4* w1_4 = (const float4*)mw1;
        float4* d1 = (float4*)s_mw1;
        for (int i = tid; i < 128 * 256 / 4; i += 256) d1[i] = w1_4[i];
        const float4* w2_4 = (const float4*)mw2;
        float4* d2 = (float4*)s_mw2;
        for (int i = tid; i < 256 * 64 / 4; i += 256) d2[i] = w2_4[i];
    }
    float r_mb1 = mb1[tid];
    float r_mb2 = (tid < 64) ? mb2[tid] : 0.f;
    if (tid < 64) s_meta[tid] = meta_init[tid];
    __syncthreads();

    for (int t = 0; t < L_; t++) {
        if (tid < 64) {
            int ai = args[b * L_ + t];
            float v = cOut[ai * E_ + tid];
            s_arg[tid] = v;
            g_arg[(b * L_ + t) * E_ + tid] = v;
        }
        __syncthreads();
        float pre = r_mb1;
#pragma unroll
        for (int a = 0; a < 64; a++) pre += s_meta[a] * s_mw1[a * H_ + tid];
#pragma unroll
        for (int e = 0; e < 64; e++) pre += s_arg[e] * s_mw1[(64 + e) * H_ + tid];
        s_h[tid] = fmaxf(pre, 0.f);
        __syncthreads();
        // split H=256 reduction 4-way: thread (a = tid&63, part = tid>>6)
        {
            int a = tid & 63;
            int base = (tid >> 6) * 64;
            float s = 0.f;
#pragma unroll
            for (int hh = 0; hh < 64; hh++)
                s += s_h[base + hh] * s_mw2[(base + hh) * A_ + a];
            s_part[tid] = s;
        }
        __syncthreads();
        if (tid < 64) {
            float nm = r_mb2 + s_part[tid] + s_part[64 + tid] +
                       s_part[128 + tid] + s_part[192 + tid];
            float nv = (ops[b * L_ + t] == 0) ? nm : s_meta[tid];
            s_meta[tid] = nv;
            g_meta[(b * L_ + t) * A_ + tid] = nv;
        }
        __syncthreads();
    }
}

// u[b,t,h] = axon_b1[h] + meta[b,t,:] @ axon_w1[64:128,:]  (parallel over b,t)
__global__ void __launch_bounds__(256) k_u(const float* __restrict__ aw1,
                                           const float* __restrict__ ab1) {
    int bt = blockIdx.x;  // 0..B*L-1
    int tid = threadIdx.x;
    __shared__ float s_m[64];
    if (tid < 64) s_m[tid] = g_meta[bt * A_ + tid];
    __syncthreads();
    float uv = ab1[tid];
#pragma unroll
    for (int a = 0; a < 64; a++) uv += s_m[a] * __ldg(&aw1[(64 + a) * H_ + tid]);
    g_u[bt * H_ + tid] = uv;
}

// attention init + zero all accumulators consumed by step 0
__global__ void k_attinit(const float* __restrict__ att_init) {
    int i = blockIdx.x * 256 + threadIdx.x;
    if (i < B_ * N_ * A_) g_att[i] = att_init[i & 63];
    if (i < B_ * A_ * H_) g_GT[i] = 0.f;
    if (i < B_ * E_ * A_) g_M[i] = 0.f;
    if (i < B_ * A_) g_attsum[i] = 0.f;
    if (i < B_) g_olmax[i] = 0;
}

// ---------------- per-step kernels ------------------------------------------

// K1: G[h,a] += relu(T1[n,h]+u[h]) * att[n,a]  over 64-row chunk (transfer only)
__global__ void __launch_bounds__(256, 2) k_G(const int* __restrict__ ops, int t) {
    int b = blockIdx.y;
    if (ops[b * L_ + t] != 2) return;
    int tid = threadIdx.x;  // h
    // block 0 zeroes g_M[b] for this step's k_M (prev k_upd already consumed it)
    if (blockIdx.x == 0) {
        float4* m4 = (float4*)&g_M[b * E_ * A_];
#pragma unroll
        for (int j = 0; j < 4; j++) m4[tid + j * 256] = make_float4(0.f, 0.f, 0.f, 0.f);
    }
    float uh = g_u[(b * L_ + t) * H_ + tid];
    __shared__ __align__(16) float4 s_att[64 * 16];  // 64 rows x 64 floats = 16KB
    int nbase = blockIdx.x * 64;
    const float4* gatt4 = (const float4*)g_att + (size_t)(b * N_ + nbase) * 16;
    float as0 = 0.f, as1 = 0.f, as2 = 0.f, as3 = 0.f;
    {
        float4 v0 = gatt4[tid], v1 = gatt4[tid + 256];
        float4 v2 = gatt4[tid + 512], v3 = gatt4[tid + 768];
        s_att[tid] = v0; s_att[tid + 256] = v1;
        s_att[tid + 512] = v2; s_att[tid + 768] = v3;
        as0 = v0.x + v1.x + v2.x + v3.x;
        as1 = v0.y + v1.y + v2.y + v3.y;
        as2 = v0.z + v1.z + v2.z + v3.z;
        as3 = v0.w + v1.w + v2.w + v3.w;
    }
    __syncthreads();
    float acc[64];
#pragma unroll
    for (int i = 0; i < 64; i++) acc[i] = 0.f;
    int n0 = nbase;
    float t1next = (n0 < C_) ? g_T1c[n0 * H_ + tid]
                             : g_T1o[(b * O_ + (n0 - C_)) * H_ + tid];
    for (int nl = 0; nl < 64; ++nl) {
        float t1 = t1next;
        if (nl < 63) {
            int n = n0 + nl + 1;
            t1next = (n < C_) ? g_T1c[n * H_ + tid]
                              : g_T1o[(b * O_ + (n - C_)) * H_ + tid];
        }
        float hv = fmaxf(t1 + uh, 0.f);
#pragma unroll
        for (int i = 0; i < 16; i++) {
            float4 w = s_att[nl * 16 + i];
            acc[4 * i + 0] += hv * w.x;
            acc[4 * i + 1] += hv * w.y;
            acc[4 * i + 2] += hv * w.z;
            acc[4 * i + 3] += hv * w.w;
        }
    }
    // transposed G => coalesced atomics (lane index = h)
#pragma unroll
    for (int a = 0; a < 64; a++)
        atomicAdd(&g_GT[(b * A_ + a) * H_ + tid], acc[a]);
    int a0 = (tid & 15) * 4;
    atomicAdd(&g_attsum[b * A_ + a0 + 0], as0);
    atomicAdd(&g_attsum[b * A_ + a0 + 1], as1);
    atomicAdd(&g_attsum[b * A_ + a0 + 2], as2);
    atomicAdd(&g_attsum[b * A_ + a0 + 3], as3);
}

// K2: M[e,a] = (W2^T G + b2 (x) attsum) / N   — partial over 16-h chunks
__global__ void __launch_bounds__(256) k_M(const int* __restrict__ ops, int t,
                                           const float* __restrict__ w2,
                                           const float* __restrict__ b2) {
    int b = blockIdx.y;
    if (ops[b * L_ + t] != 2) return;
    int h0 = blockIdx.x * 16;
    int tid = threadIdx.x;
    __shared__ float s_G[64][17];   // [a][lh], padded
    __shared__ float s_w2[16 * 64]; // [lh][e]
    for (int i = tid; i < 1024; i += 256) {
        int lh = i & 15, a = i >> 4;
        s_G[a][lh] = g_GT[(b * A_ + a) * H_ + h0 + lh];
    }
    for (int i = tid; i < 1024; i += 256) {
        int lh = i >> 6, e = i & 63;
        s_w2[lh * 64 + e] = w2[(h0 + lh) * A_ + e];  // w2 is (H,E)
    }
    __syncthreads();
    int a = tid & 63;
    int eg = tid >> 6;  // 0..3 -> e range eg*16..+15
    float acc[16];
#pragma unroll
    for (int j = 0; j < 16; j++) acc[j] = 0.f;
    for (int lh = 0; lh < 16; lh++) {
        float gv = s_G[a][lh];
#pragma unroll
        for (int j = 0; j < 16; j++) acc[j] += s_w2[lh * 64 + eg * 16 + j] * gv;
    }
    const float invN = 1.0f / (float)N_;
    if (blockIdx.x == 0) {
        float asum = g_attsum[b * A_ + a];
#pragma unroll
        for (int j = 0; j < 16; j++) acc[j] += b2[eg * 16 + j] * asum;
    }
#pragma unroll
    for (int j = 0; j < 16; j++)
        atomicAdd(&g_M[(b * E_ + eg * 16 + j) * A_ + a], acc[j] * invN);
}

// K3: attention update (insert or transfer); 32 rows per block.
// Prologue zeroes g_GT/g_attsum for the NEXT step (k_M of this step already ran).
__global__ void __launch_bounds__(512) k_upd(const int* __restrict__ ops, int t,
                                             const float* __restrict__ cIn,
                                             const float* __restrict__ cOut) {
    int tx = threadIdx.x, ty = threadIdx.y;
    int tid = ty * 64 + tx;
    {
        int gid = (blockIdx.y * gridDim.x + blockIdx.x) * 512 + tid;
        if (gid < B_ * A_ * H_) g_GT[gid] = 0.f;
        if (gid < B_ * A_) g_attsum[gid] = 0.f;
    }
    int b = blockIdx.y;
    int op = ops[b * L_ + t];
    if (op == 0) return;
    int n0 = blockIdx.x * 32;
    __shared__ __align__(16) float s_M[4096];
    __shared__ __align__(16) float s_row[2048];
    __shared__ __align__(16) float s_arg[64];
    if (op == 2) {
        float4* d = (float4*)s_M;
        const float4* s = (const float4*)(&g_M[b * 4096]);
        d[tid] = s[tid];
        d[tid + 512] = s[tid + 512];
        int r = tid >> 4, c = tid & 15, n = n0 + r;
        const float4* src = (n < C_)
            ? ((const float4*)cIn) + (size_t)n * 16
            : ((const float4*)g_objIn) + (size_t)(b * O_ + n - C_) * 16;
        ((float4*)s_row)[tid] = src[c];
    } else {
        int r = tid >> 4, c = tid & 15, n = n0 + r;
        const float4* src = (n < C_)
            ? ((const float4*)cOut) + (size_t)n * 16
            : ((const float4*)g_objOut) + (size_t)(b * O_ + n - C_) * 16;
        ((float4*)s_row)[tid] = src[c];
        if (tid < 64) s_arg[tid] = g_arg[(b * L_ + t) * E_ + tid];
    }
    __syncthreads();
    int a = tx;
    int rbase = ty * 4;
    float delta[4];
    if (op == 2) {
        float d0 = 0.f, d1 = 0.f, d2 = 0.f, d3 = 0.f;
#pragma unroll
        for (int e4 = 0; e4 < 16; e4++) {
            float m0 = s_M[(e4 * 4 + 0) * 64 + a];
            float m1 = s_M[(e4 * 4 + 1) * 64 + a];
            float m2 = s_M[(e4 * 4 + 2) * 64 + a];
            float m3 = s_M[(e4 * 4 + 3) * 64 + a];
            float4 v0 = ((float4*)s_row)[(rbase + 0) * 16 + e4];
            float4 v1 = ((float4*)s_row)[(rbase + 1) * 16 + e4];
            float4 v2 = ((float4*)s_row)[(rbase + 2) * 16 + e4];
            float4 v3 = ((float4*)s_row)[(rbase + 3) * 16 + e4];
            d0 += v0.x * m0 + v0.y * m1 + v0.z * m2 + v0.w * m3;
            d1 += v1.x * m0 + v1.y * m1 + v1.z * m2 + v1.w * m3;
            d2 += v2.x * m0 + v2.y * m1 + v2.z * m2 + v2.w * m3;
            d3 += v3.x * m0 + v3.y * m1 + v3.z * m2 + v3.w * m3;
        }
        delta[0] = d0; delta[1] = d1; delta[2] = d2; delta[3] = d3;
    } else {
        float metaA = g_meta[(b * L_ + t) * A_ + a];
#pragma unroll
        for (int r = 0; r < 4; r++) {
            float p = 0.f;
#pragma unroll
            for (int e4 = 0; e4 < 16; e4++) {
                float4 av = ((float4*)s_arg)[e4];
                float4 tv = ((float4*)s_row)[(rbase + r) * 16 + e4];
                p += av.x * tv.x + av.y * tv.y + av.z * tv.z + av.w * tv.w;
            }
            delta[r] = metaA * p * (1.0f / 64.0f);
        }
    }
#pragma unroll
    for (int r = 0; r < 4; r++) {
        size_t idx = ((size_t)(b * N_ + n0 + rbase + r)) * A_ + a;
        g_att[idx] += delta[r];
    }
}

// ---------------- epilogue ----------------------------------------------------
// Phase 1: ol[n] = mean(att[n]^2); per-batch max via atomicMax (vals >= 0)
__global__ void __launch_bounds__(256) k_ol() {
    int b = blockIdx.y;
    int n = blockIdx.x * 256 + threadIdx.x;
    __shared__ float s_red[256];
    float s = 0.f;
    if (n < N_) {
        const float4* row = (const float4*)&g_att[(size_t)(b * N_ + n) * A_];
        float acc = 0.f;
#pragma unroll
        for (int i = 0; i < 16; i++) {
            float4 v = row[i];
            acc += v.x * v.x + v.y * v.y + v.z * v.z + v.w * v.w;
        }
        s = acc * (1.0f / 64.0f);
        g_ol[b * N_ + n] = s;
    }
    s_red[threadIdx.x] = s;
    __syncthreads();
    for (int st = 128; st > 0; st >>= 1) {
        if (threadIdx.x < st)
            s_red[threadIdx.x] = fmaxf(s_red[threadIdx.x], s_red[threadIdx.x + st]);
        __syncthreads();
    }
    if (threadIdx.x == 0)
        atomicMax(&g_olmax[b], __float_as_int(s_red[0]));  // ol >= 0
}

// Phase 2: lse + write output
__global__ void __launch_bounds__(1024) k_soft(float* __restrict__ out) {
    int b = blockIdx.x;
    int tid = threadIdx.x;
    __shared__ float s_red[1024];
    float mx = __int_as_float(g_olmax[b]);
    float lsum = 0.f;
    for (int n = tid; n < N_; n += 1024) lsum += expf(g_ol[b * N_ + n] - mx);
    s_red[tid] = lsum;
    __syncthreads();
    for (int s = 512; s > 0; s >>= 1) {
        if (tid < s) s_red[tid] += s_red[tid + s];
        __syncthreads();
    }
    float lse = logf(s_red[0]) + mx;
    for (int n = tid; n < N_; n += 1024) out[b * N_ + n] = g_ol[b * N_ + n] - lse;
}

// ---------------- launch ------------------------------------------------------
extern "C" void kernel_launch(void* const* d_in, const int* in_sizes, int n_in,
                              void* d_out, int out_size) {
    const float* class_embIn   = (const float*)d_in[0];
    const float* class_embOut  = (const float*)d_in[1];
    const float* attr_embIn    = (const float*)d_in[2];
    const float* attr_embOut   = (const float*)d_in[3];
    const float* concept_embIn = (const float*)d_in[4];
    const float* concept_embOut= (const float*)d_in[5];
    const float* meta_init     = (const float*)d_in[6];
    // d_in[7] = object_init (unused by the reference)
    const float* attention_init= (const float*)d_in[8];
    const float* axon_w1       = (const float*)d_in[9];
    const float* axon_b1       = (const float*)d_in[10];
    const float* axon_w2       = (const float*)d_in[11];
    const float* axon_b2       = (const float*)d_in[12];
    const float* meta_w1       = (const float*)d_in[13];
    const float* meta_b1       = (const float*)d_in[14];
    const float* meta_w2       = (const float*)d_in[15];
    const float* meta_b2       = (const float*)d_in[16];
    const int*   program_ops   = (const int*)d_in[17];
    const int*   program_args  = (const int*)d_in[18];
    const int*   gt_classes    = (const int*)d_in[19];
    const int*   gt_attributes = (const int*)d_in[20];
    float* out = (float*)d_out;

    // k_meta needs 192KB dynamic smem
    cudaFuncSetAttribute(k_meta, cudaFuncAttributeMaxDynamicSharedMemorySize,
                         (128 * 256 + 256 * 64) * (int)sizeof(float));

    k_obj<<<dim3(32, B_), dim3(64, 4)>>>(class_embIn, class_embOut, attr_embIn,
                                         attr_embOut, gt_classes, gt_attributes);
    k_T1c<<<C_ / 8, 256>>>(concept_embOut, axon_w1);
    k_T1o<<<dim3(O_ / 8, B_), 256>>>(axon_w1);
    k_meta<<<B_, 256, (128 * 256 + 256 * 64) * sizeof(float)>>>(
        meta_init, concept_embOut, meta_w1, meta_b1, meta_w2, meta_b2,
        program_ops, program_args);
    k_u<<<B_ * L_, 256>>>(axon_w1, axon_b1);
    k_attinit<<<(B_ * N_ * A_ + 255) / 256, 256>>>(attention_init);

    for (int t = 0; t < L_; t++) {
        k_G<<<dim3(N_ / 64, B_), 256>>>(program_ops, t);
        k_M<<<dim3(H_ / 16, B_), 256>>>(program_ops, t, axon_w2, axon_b2);
        k_upd<<<dim3(N_ / 32, B_), dim3(64, 8)>>>(program_ops, t, concept_embIn,
                                                  concept_embOut);
    }
    k_ol<<<dim3((N_ + 255) / 256, B_), 256>>>();
    k_soft<<<B_, 1024>>>(out);
}

// round 3
// speedup vs baseline: 1.3755x; 1.0042x over previous
#include <cuda_runtime.h>

// Problem constants
constexpr int B_ = 8, L_ = 12, C_ = 4096, O_ = 128, N_ = 4224;
constexpr int E_ = 64, A_ = 64, H_ = 256;

// ---------------- scratch (device globals; no allocation allowed) ----------
__device__ __align__(16) float g_objIn[B_ * O_ * E_];
__device__ __align__(16) float g_objOut[B_ * O_ * E_];
__device__ __align__(16) float g_T1c[C_ * H_];        // thoughtOut(concepts) @ W1_t
__device__ __align__(16) float g_T1o[B_ * O_ * H_];   // thoughtOut(objects)  @ W1_t
__device__ __align__(16) float g_meta[B_ * L_ * A_];  // post-update meta at step t
__device__ __align__(16) float g_u[B_ * L_ * H_];     // meta @ W1_m(axon) + b1
__device__ __align__(16) float g_arg[B_ * L_ * E_];   // concept_embOut[program_args]
__device__ __align__(16) float g_att[B_ * N_ * A_];   // attention state
__device__ __align__(16) float g_GT[B_ * A_ * H_];    // G transposed: [a][h]
__device__ __align__(16) float g_attsum[B_ * A_];
__device__ __align__(16) float g_M[B_ * E_ * A_];     // 64x64 transfer matrix
__device__ __align__(16) float g_ol[B_ * N_];         // output_length
__device__ int g_olmax[B_];                            // float-as-int max (ol >= 0)

// ---------------- precompute kernels ---------------------------------------

__global__ void k_obj(const float* __restrict__ clsIn, const float* __restrict__ clsOut,
                      const float* __restrict__ atIn, const float* __restrict__ atOut,
                      const int* __restrict__ gt_cls, const int* __restrict__ gt_attr) {
    int e = threadIdx.x;              // 0..63
    int o = blockIdx.x * 4 + threadIdx.y;
    int b = blockIdx.y;
    int cls = gt_cls[b * O_ + o];
    float vi = clsIn[cls * E_ + e];
    float vo = clsOut[cls * E_ + e];
#pragma unroll
    for (int k = 0; k < 8; k++) {
        int at = gt_attr[(b * O_ + o) * 8 + k];
        vi += atIn[at * E_ + e];
        vo += atOut[at * E_ + e];
    }
    g_objIn[(b * O_ + o) * E_ + e] = vi;
    g_objOut[(b * O_ + o) * E_ + e] = vo;
}

// T1c[n,h] = concept_embOut[n,:] @ axon_w1[0:64,:]
__global__ void __launch_bounds__(256) k_T1c(const float* __restrict__ cOut,
                                             const float* __restrict__ w1) {
    int h = threadIdx.x;
    int n0 = blockIdx.x * 8;
    __shared__ float s_emb[512];
    for (int i = h; i < 512; i += 256) s_emb[i] = cOut[n0 * E_ + i];
    __syncthreads();
    float acc[8];
#pragma unroll
    for (int r = 0; r < 8; r++) acc[r] = 0.f;
    for (int e = 0; e < 64; e++) {
        float w = __ldg(&w1[e * H_ + h]);
#pragma unroll
        for (int r = 0; r < 8; r++) acc[r] += s_emb[r * 64 + e] * w;
    }
#pragma unroll
    for (int r = 0; r < 8; r++) g_T1c[(n0 + r) * H_ + h] = acc[r];
}

// T1o[b,o,h] = objOut[b,o,:] @ axon_w1[0:64,:]
__global__ void __launch_bounds__(256) k_T1o(const float* __restrict__ w1) {
    int h = threadIdx.x;
    int b = blockIdx.y;
    int o0 = blockIdx.x * 8;
    __shared__ float s_emb[512];
    for (int i = h; i < 512; i += 256) s_emb[i] = g_objOut[(b * O_ + o0) * E_ + i];
    __syncthreads();
    float acc[8];
#pragma unroll
    for (int r = 0; r < 8; r++) acc[r] = 0.f;
    for (int e = 0; e < 64; e++) {
        float w = __ldg(&w1[e * H_ + h]);
#pragma unroll
        for (int r = 0; r < 8; r++) acc[r] += s_emb[r * 64 + e] * w;
    }
#pragma unroll
    for (int r = 0; r < 8; r++) g_T1o[(b * O_ + o0 + r) * H_ + h] = acc[r];
}

// meta recurrence for all 12 steps (weights cached in smem); u moved to k_u.
__global__ void __launch_bounds__(256) k_meta(
    const float* __restrict__ meta_init, const float* __restrict__ cOut,
    const float* __restrict__ mw1, const float* __restrict__ mb1,
    const float* __restrict__ mw2, const float* __restrict__ mb2,
    const int* __restrict__ ops, const int* __restrict__ args) {
    extern __shared__ float dsm[];
    float* s_mw1 = dsm;               // 128*256 floats (128 KB)
    float* s_mw2 = dsm + 128 * 256;   // 256*64 floats  (64 KB)
    __shared__ float s_meta[64], s_arg[64], s_h[256], s_part[256];
    int b = blockIdx.x;
    int tid = threadIdx.x;

    // stage weights in smem (once)
    {
        const float4* w1_4 = (const float4*)mw1;
        float4* d1 = (float4*)s_mw1;
        for (int i = tid; i < 128 * 256 / 4; i += 256) d1[i] = w1_4[i];
        const float4* w2_4 = (const float4*)mw2;
        float4* d2 = (float4*)s_mw2;
        for (int i = tid; i < 256 * 64 / 4; i += 256) d2[i] = w2_4[i];
    }
    float r_mb1 = mb1[tid];
    float r_mb2 = (tid < 64) ? mb2[tid] : 0.f;
    if (tid < 64) s_meta[tid] = meta_init[tid];
    __syncthreads();

    for (int t = 0; t < L_; t++) {
        if (tid < 64) {
            int ai = args[b * L_ + t];
            float v = cOut[ai * E_ + tid];
            s_arg[tid] = v;
            g_arg[(b * L_ + t) * E_ + tid] = v;
        }
        __syncthreads();
        float pre = r_mb1;
#pragma unroll
        for (int a = 0; a < 64; a++) pre += s_meta[a] * s_mw1[a * H_ + tid];
#pragma unroll
        for (int e = 0; e < 64; e++) pre += s_arg[e] * s_mw1[(64 + e) * H_ + tid];
        s_h[tid] = fmaxf(pre, 0.f);
        __syncthreads();
        // split H=256 reduction 4-way: thread (a = tid&63, part = tid>>6)
        {
            int a = tid & 63;
            int base = (tid >> 6) * 64;
            float s = 0.f;
#pragma unroll
            for (int hh = 0; hh < 64; hh++)
                s += s_h[base + hh] * s_mw2[(base + hh) * A_ + a];
            s_part[tid] = s;
        }
        __syncthreads();
        if (tid < 64) {
            float nm = r_mb2 + s_part[tid] + s_part[64 + tid] +
                       s_part[128 + tid] + s_part[192 + tid];
            float nv = (ops[b * L_ + t] == 0) ? nm : s_meta[tid];
            s_meta[tid] = nv;
            g_meta[(b * L_ + t) * A_ + tid] = nv;
        }
        __syncthreads();
    }
}

// u[b,t,h] = axon_b1[h] + meta[b,t,:] @ axon_w1[64:128,:]  (parallel over b,t)
__global__ void __launch_bounds__(256) k_u(const float* __restrict__ aw1,
                                           const float* __restrict__ ab1) {
    int bt = blockIdx.x;  // 0..B*L-1
    int tid = threadIdx.x;
    __shared__ float s_m[64];
    if (tid < 64) s_m[tid] = g_meta[bt * A_ + tid];
    __syncthreads();
    float uv = ab1[tid];
#pragma unroll
    for (int a = 0; a < 64; a++) uv += s_m[a] * __ldg(&aw1[(64 + a) * H_ + tid]);
    g_u[bt * H_ + tid] = uv;
}

// attention init + zero all accumulators consumed by step 0
__global__ void k_attinit(const float* __restrict__ att_init) {
    int i = blockIdx.x * 256 + threadIdx.x;
    if (i < B_ * N_ * A_) g_att[i] = att_init[i & 63];
    if (i < B_ * A_ * H_) g_GT[i] = 0.f;
    if (i < B_ * E_ * A_) g_M[i] = 0.f;
    if (i < B_ * A_) g_attsum[i] = 0.f;
    if (i < B_) g_olmax[i] = 0;
}

// ---------------- per-step kernels ------------------------------------------

// K1: G[h,a] += relu(T1[n,h]+u[h]) * att[n,a]  over 64-row chunk (transfer only)
__global__ void __launch_bounds__(256, 2) k_G(const int* __restrict__ ops, int t) {
    int b = blockIdx.y;
    if (ops[b * L_ + t] != 2) return;
    int tid = threadIdx.x;  // h
    // block 0 zeroes g_M[b] for this step's k_M (prev k_upd already consumed it)
    if (blockIdx.x == 0) {
        float4* m4 = (float4*)&g_M[b * E_ * A_];
#pragma unroll
        for (int j = 0; j < 4; j++) m4[tid + j * 256] = make_float4(0.f, 0.f, 0.f, 0.f);
    }
    float uh = g_u[(b * L_ + t) * H_ + tid];
    __shared__ __align__(16) float4 s_att[64 * 16];  // 64 rows x 64 floats = 16KB
    int nbase = blockIdx.x * 64;
    const float4* gatt4 = (const float4*)g_att + (size_t)(b * N_ + nbase) * 16;
    float as0 = 0.f, as1 = 0.f, as2 = 0.f, as3 = 0.f;
    {
        float4 v0 = gatt4[tid], v1 = gatt4[tid + 256];
        float4 v2 = gatt4[tid + 512], v3 = gatt4[tid + 768];
        s_att[tid] = v0; s_att[tid + 256] = v1;
        s_att[tid + 512] = v2; s_att[tid + 768] = v3;
        as0 = v0.x + v1.x + v2.x + v3.x;
        as1 = v0.y + v1.y + v2.y + v3.y;
        as2 = v0.z + v1.z + v2.z + v3.z;
        as3 = v0.w + v1.w + v2.w + v3.w;
    }
    __syncthreads();
    float acc[64];
#pragma unroll
    for (int i = 0; i < 64; i++) acc[i] = 0.f;
    int n0 = nbase;
    float t1next = (n0 < C_) ? g_T1c[n0 * H_ + tid]
                             : g_T1o[(b * O_ + (n0 - C_)) * H_ + tid];
    for (int nl = 0; nl < 64; ++nl) {
        float t1 = t1next;
        if (nl < 63) {
            int n = n0 + nl + 1;
            t1next = (n < C_) ? g_T1c[n * H_ + tid]
                              : g_T1o[(b * O_ + (n - C_)) * H_ + tid];
        }
        float hv = fmaxf(t1 + uh, 0.f);
#pragma unroll
        for (int i = 0; i < 16; i++) {
            float4 w = s_att[nl * 16 + i];
            acc[4 * i + 0] += hv * w.x;
            acc[4 * i + 1] += hv * w.y;
            acc[4 * i + 2] += hv * w.z;
            acc[4 * i + 3] += hv * w.w;
        }
    }
    // transposed G => coalesced atomics (lane index = h)
#pragma unroll
    for (int a = 0; a < 64; a++)
        atomicAdd(&g_GT[(b * A_ + a) * H_ + tid], acc[a]);
    int a0 = (tid & 15) * 4;
    atomicAdd(&g_attsum[b * A_ + a0 + 0], as0);
    atomicAdd(&g_attsum[b * A_ + a0 + 1], as1);
    atomicAdd(&g_attsum[b * A_ + a0 + 2], as2);
    atomicAdd(&g_attsum[b * A_ + a0 + 3], as3);
}

// K2: M[e,a] = (W2^T G + b2 (x) attsum) / N   — partial over 16-h chunks
__global__ void __launch_bounds__(256) k_M(const int* __restrict__ ops, int t,
                                           const float* __restrict__ w2,
                                           const float* __restrict__ b2) {
    int b = blockIdx.y;
    if (ops[b * L_ + t] != 2) return;
    int h0 = blockIdx.x * 16;
    int tid = threadIdx.x;
    __shared__ float s_G[64][17];   // [a][lh], padded
    __shared__ float s_w2[16 * 64]; // [lh][e]
    for (int i = tid; i < 1024; i += 256) {
        int lh = i & 15, a = i >> 4;
        s_G[a][lh] = g_GT[(b * A_ + a) * H_ + h0 + lh];
    }
    for (int i = tid; i < 1024; i += 256) {
        int lh = i >> 6, e = i & 63;
        s_w2[lh * 64 + e] = w2[(h0 + lh) * A_ + e];  // w2 is (H,E)
    }
    __syncthreads();
    int a = tid & 63;
    int eg = tid >> 6;  // 0..3 -> e range eg*16..+15
    float acc[16];
#pragma unroll
    for (int j = 0; j < 16; j++) acc[j] = 0.f;
    for (int lh = 0; lh < 16; lh++) {
        float gv = s_G[a][lh];
#pragma unroll
        for (int j = 0; j < 16; j++) acc[j] += s_w2[lh * 64 + eg * 16 + j] * gv;
    }
    const float invN = 1.0f / (float)N_;
    if (blockIdx.x == 0) {
        float asum = g_attsum[b * A_ + a];
#pragma unroll
        for (int j = 0; j < 16; j++) acc[j] += b2[eg * 16 + j] * asum;
    }
#pragma unroll
    for (int j = 0; j < 16; j++)
        atomicAdd(&g_M[(b * E_ + eg * 16 + j) * A_ + a], acc[j] * invN);
}

// K3: attention update (insert or transfer); 32 rows per block.
// Prologue zeroes g_GT/g_attsum for the NEXT step (k_M of this step already ran).
__global__ void __launch_bounds__(512) k_upd(const int* __restrict__ ops, int t,
                                             const float* __restrict__ cIn,
                                             const float* __restrict__ cOut) {
    int tx = threadIdx.x, ty = threadIdx.y;
    int tid = ty * 64 + tx;
    {
        int gid = (blockIdx.y * gridDim.x + blockIdx.x) * 512 + tid;
        if (gid < B_ * A_ * H_) g_GT[gid] = 0.f;
        if (gid < B_ * A_) g_attsum[gid] = 0.f;
    }
    int b = blockIdx.y;
    int op = ops[b * L_ + t];
    if (op == 0) return;
    int n0 = blockIdx.x * 32;
    __shared__ __align__(16) float s_M[4096];
    __shared__ __align__(16) float s_row[2048];
    __shared__ __align__(16) float s_arg[64];
    if (op == 2) {
        float4* d = (float4*)s_M;
        const float4* s = (const float4*)(&g_M[b * 4096]);
        d[tid] = s[tid];
        d[tid + 512] = s[tid + 512];
        int r = tid >> 4, c = tid & 15, n = n0 + r;
        const float4* src = (n < C_)
            ? ((const float4*)cIn) + (size_t)n * 16
            : ((const float4*)g_objIn) + (size_t)(b * O_ + n - C_) * 16;
        ((float4*)s_row)[tid] = src[c];
    } else {
        int r = tid >> 4, c = tid & 15, n = n0 + r;
        const float4* src = (n < C_)
            ? ((const float4*)cOut) + (size_t)n * 16
            : ((const float4*)g_objOut) + (size_t)(b * O_ + n - C_) * 16;
        ((float4*)s_row)[tid] = src[c];
        if (tid < 64) s_arg[tid] = g_arg[(b * L_ + t) * E_ + tid];
    }
    __syncthreads();
    int a = tx;
    int rbase = ty * 4;
    float delta[4];
    if (op == 2) {
        float d0 = 0.f, d1 = 0.f, d2 = 0.f, d3 = 0.f;
#pragma unroll
        for (int e4 = 0; e4 < 16; e4++) {
            float m0 = s_M[(e4 * 4 + 0) * 64 + a];
            float m1 = s_M[(e4 * 4 + 1) * 64 + a];
            float m2 = s_M[(e4 * 4 + 2) * 64 + a];
            float m3 = s_M[(e4 * 4 + 3) * 64 + a];
            float4 v0 = ((float4*)s_row)[(rbase + 0) * 16 + e4];
            float4 v1 = ((float4*)s_row)[(rbase + 1) * 16 + e4];
            float4 v2 = ((float4*)s_row)[(rbase + 2) * 16 + e4];
            float4 v3 = ((float4*)s_row)[(rbase + 3) * 16 + e4];
            d0 += v0.x * m0 + v0.y * m1 + v0.z * m2 + v0.w * m3;
            d1 += v1.x * m0 + v1.y * m1 + v1.z * m2 + v1.w * m3;
            d2 += v2.x * m0 + v2.y * m1 + v2.z * m2 + v2.w * m3;
            d3 += v3.x * m0 + v3.y * m1 + v3.z * m2 + v3.w * m3;
        }
        delta[0] = d0; delta[1] = d1; delta[2] = d2; delta[3] = d3;
    } else {
        float metaA = g_meta[(b * L_ + t) * A_ + a];
#pragma unroll
        for (int r = 0; r < 4; r++) {
            float p = 0.f;
#pragma unroll
            for (int e4 = 0; e4 < 16; e4++) {
                float4 av = ((float4*)s_arg)[e4];
                float4 tv = ((float4*)s_row)[(rbase + r) * 16 + e4];
                p += av.x * tv.x + av.y * tv.y + av.z * tv.z + av.w * tv.w;
            }
            delta[r] = metaA * p * (1.0f / 64.0f);
        }
    }
#pragma unroll
    for (int r = 0; r < 4; r++) {
        size_t idx = ((size_t)(b * N_ + n0 + rbase + r)) * A_ + a;
        g_att[idx] += delta[r];
    }
}

// ---------------- epilogue ----------------------------------------------------
// Phase 1: ol[n] = mean(att[n]^2); per-batch max via atomicMax (vals >= 0)
__global__ void __launch_bounds__(256) k_ol() {
    int b = blockIdx.y;
    int n = blockIdx.x * 256 + threadIdx.x;
    __shared__ float s_red[256];
    float s = 0.f;
    if (n < N_) {
        const float4* row = (const float4*)&g_att[(size_t)(b * N_ + n) * A_];
        float acc = 0.f;
#pragma unroll
        for (int i = 0; i < 16; i++) {
            float4 v = row[i];
            acc += v.x * v.x + v.y * v.y + v.z * v.z + v.w * v.w;
        }
        s = acc * (1.0f / 64.0f);
        g_ol[b * N_ + n] = s;
    }
    s_red[threadIdx.x] = s;
    __syncthreads();
    for (int st = 128; st > 0; st >>= 1) {
        if (threadIdx.x < st)
            s_red[threadIdx.x] = fmaxf(s_red[threadIdx.x], s_red[threadIdx.x + st]);
        __syncthreads();
    }
    if (threadIdx.x == 0)
        atomicMax(&g_olmax[b], __float_as_int(s_red[0]));  // ol >= 0
}

// Phase 2: lse + write output
__global__ void __launch_bounds__(1024) k_soft(float* __restrict__ out) {
    int b = blockIdx.x;
    int tid = threadIdx.x;
    __shared__ float s_red[1024];
    float mx = __int_as_float(g_olmax[b]);
    float lsum = 0.f;
    for (int n = tid; n < N_; n += 1024) lsum += expf(g_ol[b * N_ + n] - mx);
    s_red[tid] = lsum;
    __syncthreads();
    for (int s = 512; s > 0; s >>= 1) {
        if (tid < s) s_red[tid] += s_red[tid + s];
        __syncthreads();
    }
    float lse = logf(s_red[0]) + mx;
    for (int n = tid; n < N_; n += 1024) out[b * N_ + n] = g_ol[b * N_ + n] - lse;
}

// ---------------- launch ------------------------------------------------------
extern "C" void kernel_launch(void* const* d_in, const int* in_sizes, int n_in,
                              void* d_out, int out_size) {
    const float* class_embIn   = (const float*)d_in[0];
    const float* class_embOut  = (const float*)d_in[1];
    const float* attr_embIn    = (const float*)d_in[2];
    const float* attr_embOut   = (const float*)d_in[3];
    const float* concept_embIn = (const float*)d_in[4];
    const float* concept_embOut= (const float*)d_in[5];
    const float* meta_init     = (const float*)d_in[6];
    // d_in[7] = object_init (unused by the reference)
    const float* attention_init= (const float*)d_in[8];
    const float* axon_w1       = (const float*)d_in[9];
    const float* axon_b1       = (const float*)d_in[10];
    const float* axon_w2       = (const float*)d_in[11];
    const float* axon_b2       = (const float*)d_in[12];
    const float* meta_w1       = (const float*)d_in[13];
    const float* meta_b1       = (const float*)d_in[14];
    const float* meta_w2       = (const float*)d_in[15];
    const float* meta_b2       = (const float*)d_in[16];
    const int*   program_ops   = (const int*)d_in[17];
    const int*   program_args  = (const int*)d_in[18];
    const int*   gt_classes    = (const int*)d_in[19];
    const int*   gt_attributes = (const int*)d_in[20];
    float* out = (float*)d_out;

    // k_meta needs 192KB dynamic smem
    cudaFuncSetAttribute(k_meta, cudaFuncAttributeMaxDynamicSharedMemorySize,
                         (128 * 256 + 256 * 64) * (int)sizeof(float));

    k_obj<<<dim3(32, B_), dim3(64, 4)>>>(class_embIn, class_embOut, attr_embIn,
                                         attr_embOut, gt_classes, gt_attributes);
    k_T1c<<<C_ / 8, 256>>>(concept_embOut, axon_w1);
    k_T1o<<<dim3(O_ / 8, B_), 256>>>(axon_w1);
    k_meta<<<B_, 256, (128 * 256 + 256 * 64) * sizeof(float)>>>(
        meta_init, concept_embOut, meta_w1, meta_b1, meta_w2, meta_b2,
        program_ops, program_args);
    k_u<<<B_ * L_, 256>>>(axon_w1, axon_b1);
    k_attinit<<<(B_ * N_ * A_ + 255) / 256, 256>>>(attention_init);

    for (int t = 0; t < L_; t++) {
        k_G<<<dim3(N_ / 64, B_), 256>>>(program_ops, t);
        k_M<<<dim3(H_ / 16, B_), 256>>>(program_ops, t, axon_w2, axon_b2);
        k_upd<<<dim3(N_ / 32, B_), dim3(64, 8)>>>(program_ops, t, concept_embIn,
                                                  concept_embOut);
    }
    k_ol<<<dim3((N_ + 255) / 256, B_), 256>>>();
    k_soft<<<B_, 1024>>>(out);
}

// round 4
// speedup vs baseline: 1.6917x; 1.2299x over previous
#include <cuda_runtime.h>

// Problem constants
constexpr int B_ = 8, L_ = 12, C_ = 4096, O_ = 128, N_ = 4224;
constexpr int E_ = 64, A_ = 64, H_ = 256;
constexpr int DCOLS = 80;  // X cols: 0..63 tIn, 64..75 proj_s, 76 = ones(S), 77..79 pad

// ---------------- scratch (device globals) ----------------------------------
__device__ __align__(16) float g_objIn[B_ * O_ * E_];
__device__ __align__(16) float g_objOut[B_ * O_ * E_];
__device__ __align__(16) float g_T1c[C_ * H_];        // conceptsOut @ axon_w1[0:64]
__device__ __align__(16) float g_T1o[B_ * O_ * H_];   // objOut @ axon_w1[0:64]
__device__ __align__(16) float g_meta[B_ * L_ * A_];
__device__ __align__(16) float g_u[B_ * L_ * H_];     // axon hidden bias per (b,t)
__device__ __align__(16) float g_arg[B_ * L_ * E_];
__device__ __align__(16) float g_parg[B_ * L_ * H_];  // meta_b1 + arg @ meta_w1[64:128]
__device__ __align__(16) float g_proj[B_ * N_ * 16];  // [0..11]=proj_s, [12]=1, pad
__device__ __align__(16) float g_psum[B_ * 16];       // sum_n proj_s[n]
__device__ __align__(16) float g_tInsum[B_ * E_];     // sum_n tIn[n,e]
__device__ __align__(16) float g_D[B_ * L_ * H_ * DCOLS];  // [bt][h][c]
__device__ __align__(16) float g_Msum[B_ * E_ * A_];
__device__ __align__(16) float g_ol[B_ * N_];
__device__ int g_olmax[B_];

// ---------------- zero accumulators -----------------------------------------
__global__ void k_zero() {
    int i = blockIdx.x * 256 + threadIdx.x;
    float4 z = make_float4(0.f, 0.f, 0.f, 0.f);
    if (i < B_ * L_ * H_ * DCOLS / 4) ((float4*)g_D)[i] = z;
    if (i < B_ * 16) g_psum[i] = 0.f;
    if (i < B_ * E_) g_tInsum[i] = 0.f;
    if (i < B_) g_olmax[i] = 0;
}

// ---------------- precompute -------------------------------------------------
__global__ void k_obj(const float* __restrict__ clsIn, const float* __restrict__ clsOut,
                      const float* __restrict__ atIn, const float* __restrict__ atOut,
                      const int* __restrict__ gt_cls, const int* __restrict__ gt_attr) {
    int e = threadIdx.x;
    int o = blockIdx.x * 4 + threadIdx.y;
    int b = blockIdx.y;
    int cls = gt_cls[b * O_ + o];
    float vi = clsIn[cls * E_ + e];
    float vo = clsOut[cls * E_ + e];
#pragma unroll
    for (int k = 0; k < 8; k++) {
        int at = gt_attr[(b * O_ + o) * 8 + k];
        vi += atIn[at * E_ + e];
        vo += atOut[at * E_ + e];
    }
    g_objIn[(b * O_ + o) * E_ + e] = vi;
    g_objOut[(b * O_ + o) * E_ + e] = vo;
}

__global__ void __launch_bounds__(256) k_T1c(const float* __restrict__ cOut,
                                             const float* __restrict__ w1) {
    int h = threadIdx.x;
    int n0 = blockIdx.x * 8;
    __shared__ float s_emb[512];
    for (int i = h; i < 512; i += 256) s_emb[i] = cOut[n0 * E_ + i];
    __syncthreads();
    float acc[8];
#pragma unroll
    for (int r = 0; r < 8; r++) acc[r] = 0.f;
    for (int e = 0; e < 64; e++) {
        float w = __ldg(&w1[e * H_ + h]);
#pragma unroll
        for (int r = 0; r < 8; r++) acc[r] += s_emb[r * 64 + e] * w;
    }
#pragma unroll
    for (int r = 0; r < 8; r++) g_T1c[(n0 + r) * H_ + h] = acc[r];
}

__global__ void __launch_bounds__(256) k_T1o(const float* __restrict__ w1) {
    int h = threadIdx.x;
    int b = blockIdx.y;
    int o0 = blockIdx.x * 8;
    __shared__ float s_emb[512];
    for (int i = h; i < 512; i += 256) s_emb[i] = g_objOut[(b * O_ + o0) * E_ + i];
    __syncthreads();
    float acc[8];
#pragma unroll
    for (int r = 0; r < 8; r++) acc[r] = 0.f;
    for (int e = 0; e < 64; e++) {
        float w = __ldg(&w1[e * H_ + h]);
#pragma unroll
        for (int r = 0; r < 8; r++) acc[r] += s_emb[r * 64 + e] * w;
    }
#pragma unroll
    for (int r = 0; r < 8; r++) g_T1o[(b * O_ + o0 + r) * H_ + h] = acc[r];
}

// gather args
__global__ void k_arg(const float* __restrict__ cOut, const int* __restrict__ args) {
    int i = blockIdx.x * 256 + threadIdx.x;
    if (i < B_ * L_ * E_) {
        int bt = i >> 6, e = i & 63;
        g_arg[i] = cOut[args[bt] * E_ + e];
    }
}

// parg[bt,h] = meta_b1[h] + arg @ meta_w1[64:128,:]
__global__ void __launch_bounds__(256) k_parg(const float* __restrict__ mw1,
                                              const float* __restrict__ mb1) {
    int bt = blockIdx.x;
    int h = threadIdx.x;
    __shared__ float s_a[64];
    if (h < 64) s_a[h] = g_arg[bt * E_ + h];
    __syncthreads();
    float p = mb1[h];
#pragma unroll
    for (int e = 0; e < 64; e++) p += s_a[e] * __ldg(&mw1[(64 + e) * H_ + h]);
    g_parg[bt * H_ + h] = p;
}

// meta recurrence; only meta-half of w1 needed (arg half precomputed in parg)
__global__ void __launch_bounds__(256) k_meta(
    const float* __restrict__ meta_init,
    const float* __restrict__ mw1, const float* __restrict__ mw2,
    const float* __restrict__ mb2, const int* __restrict__ ops) {
    extern __shared__ float dsm[];
    float* s_w1a = dsm;            // 64*256
    float* s_w2m = dsm + 16384;    // 256*64
    __shared__ float s_meta[64], s_h[256], s_part[256];
    int b = blockIdx.x;
    int tid = threadIdx.x;
    {
        const float4* w1_4 = (const float4*)mw1;  // rows 0..63 are first 16384 floats
        float4* d1 = (float4*)s_w1a;
        for (int i = tid; i < 4096; i += 256) d1[i] = w1_4[i];
        const float4* w2_4 = (const float4*)mw2;
        float4* d2 = (float4*)s_w2m;
        for (int i = tid; i < 4096; i += 256) d2[i] = w2_4[i];
    }
    float r_mb2 = (tid < 64) ? mb2[tid] : 0.f;
    if (tid < 64) s_meta[tid] = meta_init[tid];
    __syncthreads();
    for (int t = 0; t < L_; t++) {
        float pre = g_parg[(b * L_ + t) * H_ + tid];
#pragma unroll
        for (int a = 0; a < 64; a++) pre += s_meta[a] * s_w1a[a * H_ + tid];
        s_h[tid] = fmaxf(pre, 0.f);
        __syncthreads();
        {
            int a = tid & 63;
            int base = (tid >> 6) * 64;
            float s = 0.f;
#pragma unroll
            for (int hh = 0; hh < 64; hh++)
                s += s_h[base + hh] * s_w2m[(base + hh) * A_ + a];
            s_part[tid] = s;
        }
        __syncthreads();
        if (tid < 64) {
            float nm = r_mb2 + s_part[tid] + s_part[64 + tid] +
                       s_part[128 + tid] + s_part[192 + tid];
            float nv = (ops[b * L_ + t] == 0) ? nm : s_meta[tid];
            s_meta[tid] = nv;
            g_meta[(b * L_ + t) * A_ + tid] = nv;
        }
        __syncthreads();
    }
}

// u[bt,h] = axon_b1[h] + meta[bt] @ axon_w1[64:128,:]
__global__ void __launch_bounds__(256) k_u(const float* __restrict__ aw1,
                                           const float* __restrict__ ab1) {
    int bt = blockIdx.x;
    int tid = threadIdx.x;
    __shared__ float s_m[64];
    if (tid < 64) s_m[tid] = g_meta[bt * A_ + tid];
    __syncthreads();
    float uv = ab1[tid];
#pragma unroll
    for (int a = 0; a < 64; a++) uv += s_m[a] * __ldg(&aw1[(64 + a) * H_ + tid]);
    g_u[bt * H_ + tid] = uv;
}

// proj_s[b,n] = (arg_s . thoughtOut[n]) / 64  for all 12 s; also psum
__global__ void __launch_bounds__(256) k_proj(const float* __restrict__ cOut) {
    int b = blockIdx.y;
    int tid = threadIdx.x;
    int w = tid >> 5, lane = tid & 31;
    __shared__ float s_arg[768];
    __shared__ float s_p[8][16];
    for (int i = tid; i < 768; i += 256) s_arg[i] = g_arg[b * 768 + i];
    __syncthreads();
    int n = blockIdx.x * 8 + w;
    const float* row = (n < C_) ? cOut + (size_t)n * 64
                                : g_objOut + (size_t)(b * O_ + n - C_) * 64;
    float x0 = row[lane], x1 = row[lane + 32];
#pragma unroll
    for (int s = 0; s < 12; s++) {
        float p = x0 * s_arg[s * 64 + lane] + x1 * s_arg[s * 64 + 32 + lane];
#pragma unroll
        for (int o = 16; o > 0; o >>= 1) p += __shfl_xor_sync(0xffffffffu, p, o);
        if (lane == 0) s_p[w][s] = p * (1.0f / 64.0f);
    }
    __syncwarp();
    if (lane < 16) {
        float v = (lane < 12) ? s_p[w][lane] : ((lane == 12) ? 1.0f : 0.0f);
        g_proj[(size_t)(b * N_ + n) * 16 + lane] = v;
        if (lane < 12) atomicAdd(&g_psum[b * 16 + lane], v);
    }
}

// tInsum[b,e] = sum_n thoughtIn[n,e]
__global__ void __launch_bounds__(64) k_tinsum(const float* __restrict__ cIn) {
    int b = blockIdx.y;
    int e = threadIdx.x;
    int n0 = blockIdx.x * 64;
    float s = 0.f;
    for (int r = 0; r < 64; r++) {
        int n = n0 + r;
        const float* row = (n < C_) ? cIn + (size_t)n * 64
                                    : g_objIn + (size_t)(b * O_ + n - C_) * 64;
        s += row[e];
    }
    atomicAdd(&g_tInsum[b * E_ + e], s);
}

// ---------------- big GEMM: D_t = Hrel_t^T @ [tIn | proj | 1] ----------------
__global__ void __launch_bounds__(256) k_D(const int* __restrict__ ops,
                                           const float* __restrict__ cIn) {
    int t = blockIdx.y, b = blockIdx.z;
    if (ops[b * L_ + t] != 2) return;
    int h = threadIdx.x;
    __shared__ __align__(16) float s_X[64 * 80];
    float uh = g_u[(b * L_ + t) * H_ + h];
    unsigned long long acc[40];
#pragma unroll
    for (int j = 0; j < 40; j++) acc[j] = 0ULL;
    int nbase = blockIdx.x * 192;
    for (int tile = 0; tile < 3; tile++) {
        int n0 = nbase + tile * 64;
        {
            float4* dst = (float4*)s_X;
            for (int i = h; i < 1024; i += 256) {
                int r = i >> 4, c = i & 15;
                int n = n0 + r;
                const float4* src = (n < C_)
                    ? (const float4*)cIn + (size_t)n * 16
                    : (const float4*)g_objIn + (size_t)(b * O_ + n - C_) * 16;
                dst[r * 20 + c] = src[c];
            }
            {
                int r = h >> 2, c = h & 3;  // 256 threads -> 64 rows x 4
                dst[r * 20 + 16 + c] =
                    ((const float4*)g_proj)[(size_t)(b * N_ + n0 + r) * 4 + c];
            }
        }
        __syncthreads();
        float t1n = (n0 < C_) ? g_T1c[n0 * H_ + h]
                              : g_T1o[(b * O_ + n0 - C_) * H_ + h];
        for (int nl = 0; nl < 64; nl++) {
            float t1 = t1n;
            if (nl < 63) {
                int n = n0 + nl + 1;
                t1n = (n < C_) ? g_T1c[n * H_ + h]
                               : g_T1o[(b * O_ + n - C_) * H_ + h];
            }
            float hv = fmaxf(t1 + uh, 0.f);
            unsigned int hb = __float_as_uint(hv);
            unsigned long long hv2 = ((unsigned long long)hb << 32) | hb;
            const ulonglong2* xr = (const ulonglong2*)(s_X + nl * 80);
#pragma unroll
            for (int j = 0; j < 20; j++) {
                ulonglong2 p = xr[j];
                asm("fma.rn.f32x2 %0, %1, %2, %0;" : "+l"(acc[2 * j]) : "l"(hv2), "l"(p.x));
                asm("fma.rn.f32x2 %0, %1, %2, %0;" : "+l"(acc[2 * j + 1]) : "l"(hv2), "l"(p.y));
            }
        }
        __syncthreads();
    }
    float* dp = g_D + ((size_t)(b * L_ + t) * H_ + h) * DCOLS;
#pragma unroll
    for (int j = 0; j < 40; j++) {
        float lo = __uint_as_float((unsigned)(acc[j] & 0xffffffffULL));
        float hi = __uint_as_float((unsigned)(acc[j] >> 32));
        asm volatile("red.global.add.v2.f32 [%0], {%1, %2};"
                     :: "l"(dp + 2 * j), "f"(lo), "f"(hi) : "memory");
    }
}

// ---------------- small recurrence: M_t, attsum, Msum -------------------------
__global__ void __launch_bounds__(1024) k_rec(const int* __restrict__ ops,
                                              const float* __restrict__ w2,
                                              const float* __restrict__ b2,
                                              const float* __restrict__ att_init) {
    extern __shared__ float dsm[];
    float* s_w2 = dsm;              // 16384
    float* s_G = dsm + 16384;       // 64*257 = 16448, layout [a][h] pitch 257
    float* s_Ms = dsm + 32832;      // 4096, [e][a]
    float* s_tmp = dsm + 36928;     // 1024
    __shared__ float s_meta[768], s_as[64], s_ai[64], s_tis[64], s_b2[64], s_ps[12];
    __shared__ int s_op[12];
    int b = blockIdx.x, tid = threadIdx.x;
    for (int i = tid; i < 16384; i += 1024) s_w2[i] = w2[i];
    for (int i = tid; i < 4096; i += 1024) s_Ms[i] = 0.f;
    if (tid < 768) s_meta[tid] = g_meta[b * 768 + tid];
    if (tid < 64) {
        s_ai[tid] = att_init[tid];
        s_as[tid] = (float)N_ * att_init[tid];
        s_tis[tid] = g_tInsum[b * 64 + tid];
        s_b2[tid] = b2[tid];
    }
    if (tid < 12) { s_op[tid] = ops[b * L_ + tid]; s_ps[tid] = g_psum[b * 16 + tid]; }
    __syncthreads();
    const float invN = 1.0f / (float)N_;
    for (int t = 0; t < L_; t++) {
        int op = s_op[t];
        if (op == 1) {
            if (tid < 64) s_as[tid] += s_ps[t] * s_meta[t * 64 + tid];
            __syncthreads();
        } else if (op == 2) {
            const float* Drow =
                g_D + ((size_t)(b * L_ + t) * H_ + (tid & 255)) * DCOLS;
            int h = tid & 255, q = tid >> 8;
            // G init: S*att_init + inserts
            float S = Drow[76];
            float ini[16];
#pragma unroll
            for (int j = 0; j < 16; j++) ini[j] = S * s_ai[q * 16 + j];
            for (int s = 0; s < t; s++)
                if (s_op[s] == 1) {
                    float R = Drow[64 + s];
#pragma unroll
                    for (int j = 0; j < 16; j++)
                        ini[j] += R * s_meta[s * 64 + q * 16 + j];
                }
            unsigned long long acc2[8];
#pragma unroll
            for (int k = 0; k < 8; k++)
                acc2[k] = ((unsigned long long)__float_as_uint(ini[2 * k + 1]) << 32) |
                          __float_as_uint(ini[2 * k]);
            // K @ Msum_pre
            const float4* K4 = (const float4*)Drow;
#pragma unroll
            for (int e4 = 0; e4 < 16; e4++) {
                float4 kv = K4[e4];
                float kc[4] = {kv.x, kv.y, kv.z, kv.w};
#pragma unroll
                for (int c = 0; c < 4; c++) {
                    int e = e4 * 4 + c;
                    unsigned int kb = __float_as_uint(kc[c]);
                    unsigned long long k2 = ((unsigned long long)kb << 32) | kb;
                    const ulonglong2* M2 =
                        (const ulonglong2*)s_Ms + e * 16 + q * 4;
#pragma unroll
                    for (int kk = 0; kk < 4; kk++) {
                        ulonglong2 m = M2[kk];
                        asm("fma.rn.f32x2 %0, %1, %2, %0;"
                            : "+l"(acc2[2 * kk]) : "l"(k2), "l"(m.x));
                        asm("fma.rn.f32x2 %0, %1, %2, %0;"
                            : "+l"(acc2[2 * kk + 1]) : "l"(k2), "l"(m.y));
                    }
                }
            }
#pragma unroll
            for (int k = 0; k < 8; k++) {
                s_G[(q * 16 + 2 * k) * 257 + h] =
                    __uint_as_float((unsigned)(acc2[k] & 0xffffffffULL));
                s_G[(q * 16 + 2 * k + 1) * 257 + h] =
                    __uint_as_float((unsigned)(acc2[k] >> 32));
            }
            __syncthreads();
            // M_t[e,a] = (W2^T G + b2*attsum)/N ; threads (a, eg) own e=eg*4..+3
            int a = tid & 63, eg = tid >> 6;
            unsigned long long am[2] = {0ULL, 0ULL};
            const ulonglong2* W2v = (const ulonglong2*)s_w2;
#pragma unroll 4
            for (int h2 = 0; h2 < 256; h2++) {
                unsigned int gb = __float_as_uint(s_G[a * 257 + h2]);
                unsigned long long g2 = ((unsigned long long)gb << 32) | gb;
                ulonglong2 w = W2v[h2 * 16 + eg];
                asm("fma.rn.f32x2 %0, %1, %2, %0;" : "+l"(am[0]) : "l"(g2), "l"(w.x));
                asm("fma.rn.f32x2 %0, %1, %2, %0;" : "+l"(am[1]) : "l"(g2), "l"(w.y));
            }
            float accM[4] = {
                __uint_as_float((unsigned)(am[0] & 0xffffffffULL)),
                __uint_as_float((unsigned)(am[0] >> 32)),
                __uint_as_float((unsigned)(am[1] & 0xffffffffULL)),
                __uint_as_float((unsigned)(am[1] >> 32))};
            float asv = s_as[a];
            float part = 0.f;
#pragma unroll
            for (int j = 0; j < 4; j++) {
                int e = eg * 4 + j;
                float m = (accM[j] + s_b2[e] * asv) * invN;
                s_Ms[e * 64 + a] += m;
                part += s_tis[e] * m;
            }
            s_tmp[eg * 64 + a] = part;
            __syncthreads();
            if (tid < 64) {
                float d = 0.f;
#pragma unroll
                for (int g = 0; g < 16; g++) d += s_tmp[g * 64 + tid];
                s_as[tid] += d;
            }
            __syncthreads();
        }
    }
    for (int i = tid; i < 4096; i += 1024) g_Msum[b * 4096 + i] = s_Ms[i];
}

// ---------------- final: reconstruct att rows, ol = mean(att^2), max ---------
__global__ void __launch_bounds__(128) k_final(const int* __restrict__ ops,
                                               const float* __restrict__ cIn,
                                               const float* __restrict__ att_init) {
    int b = blockIdx.y;
    int ag = threadIdx.x;           // 0..15 -> a = ag*4..+3
    int ny = threadIdx.y;           // 0..7
    int tid = ny * 16 + ag;
    __shared__ float s_Ms[4096], s_meta[768], s_ai[64];
    __shared__ float s_ti[8][64], s_pr[8][16], s_half[8];
    __shared__ int s_opf[12];
    for (int i = tid; i < 4096; i += 128) s_Ms[i] = g_Msum[b * 4096 + i];
    for (int i = tid; i < 768; i += 128) s_meta[i] = g_meta[b * 768 + i];
    if (tid < 64) s_ai[tid] = att_init[tid];
    if (tid < 12) s_opf[tid] = ops[b * L_ + tid];
    int n0 = blockIdx.x * 8;
    for (int i = tid; i < 512; i += 128) {
        int r = i >> 6, e = i & 63;
        int n = n0 + r;
        const float* row = (n < C_) ? cIn + (size_t)n * 64
                                    : g_objIn + (size_t)(b * O_ + n - C_) * 64;
        s_ti[r][e] = row[e];
    }
    {
        int r = tid >> 4, c = tid & 15;
        s_pr[r][c] = g_proj[(size_t)(b * N_ + n0 + r) * 16 + c];
    }
    __syncthreads();
    int n = n0 + ny;
    int a0 = ag * 4;
    float v0 = s_ai[a0], v1 = s_ai[a0 + 1], v2 = s_ai[a0 + 2], v3 = s_ai[a0 + 3];
#pragma unroll
    for (int s = 0; s < 12; s++)
        if (s_opf[s] == 1) {
            float pp = s_pr[ny][s];
            v0 += pp * s_meta[s * 64 + a0];
            v1 += pp * s_meta[s * 64 + a0 + 1];
            v2 += pp * s_meta[s * 64 + a0 + 2];
            v3 += pp * s_meta[s * 64 + a0 + 3];
        }
    const float4* Ms4 = (const float4*)s_Ms;
#pragma unroll
    for (int e = 0; e < 64; e++) {
        float ti = s_ti[ny][e];
        float4 m = Ms4[e * 16 + ag];
        v0 += ti * m.x; v1 += ti * m.y; v2 += ti * m.z; v3 += ti * m.w;
    }
    float sq = v0 * v0 + v1 * v1 + v2 * v2 + v3 * v3;
#pragma unroll
    for (int o = 8; o > 0; o >>= 1) sq += __shfl_xor_sync(0xffffffffu, sq, o);
    if (ag == 0) {
        float ol = sq * (1.0f / 64.0f);
        g_ol[b * N_ + n] = ol;
        atomicMax(&g_olmax[b], __float_as_int(ol));  // ol >= 0
    }
}

__global__ void __launch_bounds__(1024) k_soft(float* __restrict__ out) {
    int b = blockIdx.x;
    int tid = threadIdx.x;
    __shared__ float s_red[1024];
    float mx = __int_as_float(g_olmax[b]);
    float lsum = 0.f;
    for (int n = tid; n < N_; n += 1024) lsum += expf(g_ol[b * N_ + n] - mx);
    s_red[tid] = lsum;
    __syncthreads();
    for (int s = 512; s > 0; s >>= 1) {
        if (tid < s) s_red[tid] += s_red[tid + s];
        __syncthreads();
    }
    float lse = logf(s_red[0]) + mx;
    for (int n = tid; n < N_; n += 1024) out[b * N_ + n] = g_ol[b * N_ + n] - lse;
}

// ---------------- launch ------------------------------------------------------
extern "C" void kernel_launch(void* const* d_in, const int* in_sizes, int n_in,
                              void* d_out, int out_size) {
    const float* class_embIn   = (const float*)d_in[0];
    const float* class_embOut  = (const float*)d_in[1];
    const float* attr_embIn    = (const float*)d_in[2];
    const float* attr_embOut   = (const float*)d_in[3];
    const float* concept_embIn = (const float*)d_in[4];
    const float* concept_embOut= (const float*)d_in[5];
    const float* meta_init     = (const float*)d_in[6];
    const float* attention_init= (const float*)d_in[8];
    const float* axon_w1       = (const float*)d_in[9];
    const float* axon_b1       = (const float*)d_in[10];
    const float* axon_w2       = (const float*)d_in[11];
    const float* axon_b2       = (const float*)d_in[12];
    const float* meta_w1       = (const float*)d_in[13];
    const float* meta_b1       = (const float*)d_in[14];
    const float* meta_w2       = (const float*)d_in[15];
    const float* meta_b2       = (const float*)d_in[16];
    const int*   program_ops   = (const int*)d_in[17];
    const int*   program_args  = (const int*)d_in[18];
    const int*   gt_classes    = (const int*)d_in[19];
    const int*   gt_attributes = (const int*)d_in[20];
    float* out = (float*)d_out;

    cudaFuncSetAttribute(k_meta, cudaFuncAttributeMaxDynamicSharedMemorySize,
                         32768 * (int)sizeof(float));
    cudaFuncSetAttribute(k_rec, cudaFuncAttributeMaxDynamicSharedMemorySize,
                         37952 * (int)sizeof(float));

    k_zero<<<(B_ * L_ * H_ * DCOLS / 4 + 255) / 256, 256>>>();
    k_obj<<<dim3(32, B_), dim3(64, 4)>>>(class_embIn, class_embOut, attr_embIn,
                                         attr_embOut, gt_classes, gt_attributes);
    k_T1c<<<C_ / 8, 256>>>(concept_embOut, axon_w1);
    k_T1o<<<dim3(O_ / 8, B_), 256>>>(axon_w1);
    k_arg<<<(B_ * L_ * E_ + 255) / 256, 256>>>(concept_embOut, program_args);
    k_parg<<<B_ * L_, 256>>>(meta_w1, meta_b1);
    k_meta<<<B_, 256, 32768 * sizeof(float)>>>(meta_init, meta_w1, meta_w2,
                                               meta_b2, program_ops);
    k_u<<<B_ * L_, 256>>>(axon_w1, axon_b1);
    k_proj<<<dim3(N_ / 8, B_), 256>>>(concept_embOut);
    k_tinsum<<<dim3(N_ / 64, B_), 64>>>(concept_embIn);
    k_D<<<dim3(N_ / 192, L_, B_), 256>>>(program_ops, concept_embIn);
    k_rec<<<B_, 1024, 37952 * sizeof(float)>>>(program_ops, axon_w2, axon_b2,
                                               attention_init);
    k_final<<<dim3(N_ / 8, B_), dim3(16, 8)>>>(program_ops, concept_embIn,
                                               attention_init);
    k_soft<<<B_, 1024>>>(out);
}

// round 6
// speedup vs baseline: 2.0979x; 1.2401x over previous
#include <cuda_runtime.h>

// Problem constants
constexpr int B_ = 8, L_ = 12, C_ = 4096, O_ = 128, N_ = 4224;
constexpr int E_ = 64, A_ = 64, H_ = 256;
constexpr int DCOLS = 80;  // X cols: 0..63 tIn, 64..75 proj_s, 76 = ones, 77..79 pad

// ---------------- scratch (device globals) ----------------------------------
__device__ __align__(16) float g_objIn[B_ * O_ * E_];
__device__ __align__(16) float g_objOut[B_ * O_ * E_];
__device__ __align__(16) float g_T1c[C_ * H_];
__device__ __align__(16) float g_T1o[B_ * O_ * H_];
__device__ __align__(16) float g_meta[B_ * L_ * A_];
__device__ __align__(16) float g_u[B_ * L_ * H_];
__device__ __align__(16) float g_arg[B_ * L_ * E_];
__device__ __align__(16) float g_parg[B_ * L_ * H_];
__device__ __align__(16) float g_proj[B_ * N_ * 16];
__device__ __align__(16) float g_psum[B_ * 16];
__device__ __align__(16) float g_tInsum[B_ * E_];
__device__ __align__(16) float g_D[B_ * L_ * H_ * DCOLS];   // [bt][h][c]
__device__ __align__(16) float g_E[B_ * L_ * DCOLS * 64];   // [bt][c][e'] (transposed)
__device__ __align__(16) float g_Msum[B_ * E_ * A_];
__device__ __align__(16) float g_ol[B_ * N_];
__device__ int g_olmax[B_];

__device__ __forceinline__ unsigned long long pack2(float v) {
    unsigned int b = __float_as_uint(v);
    return ((unsigned long long)b << 32) | b;
}
__device__ __forceinline__ float lo2(unsigned long long v) {
    return __uint_as_float((unsigned)(v & 0xffffffffULL));
}
__device__ __forceinline__ float hi2(unsigned long long v) {
    return __uint_as_float((unsigned)(v >> 32));
}

// ---------------- zero accumulators -----------------------------------------
__global__ void k_zero() {
    int i = blockIdx.x * 256 + threadIdx.x;
    float4 z = make_float4(0.f, 0.f, 0.f, 0.f);
    if (i < B_ * L_ * H_ * DCOLS / 4) ((float4*)g_D)[i] = z;
    if (i < B_ * 16) g_psum[i] = 0.f;
    if (i < B_ * E_) g_tInsum[i] = 0.f;
    if (i < B_) g_olmax[i] = 0;
}

// ---------------- precompute -------------------------------------------------
__global__ void k_obj(const float* __restrict__ clsIn, const float* __restrict__ clsOut,
                      const float* __restrict__ atIn, const float* __restrict__ atOut,
                      const int* __restrict__ gt_cls, const int* __restrict__ gt_attr) {
    int e = threadIdx.x;
    int o = blockIdx.x * 4 + threadIdx.y;
    int b = blockIdx.y;
    int cls = gt_cls[b * O_ + o];
    float vi = clsIn[cls * E_ + e];
    float vo = clsOut[cls * E_ + e];
#pragma unroll
    for (int k = 0; k < 8; k++) {
        int at = gt_attr[(b * O_ + o) * 8 + k];
        vi += atIn[at * E_ + e];
        vo += atOut[at * E_ + e];
    }
    g_objIn[(b * O_ + o) * E_ + e] = vi;
    g_objOut[(b * O_ + o) * E_ + e] = vo;
}

// T1c[n,h] = concept_embOut[n,:] @ axon_w1[0:64,:]  (w1 staged in smem chunks)
__global__ void __launch_bounds__(256) k_T1c(const float* __restrict__ cOut,
                                             const float* __restrict__ w1) {
    int h = threadIdx.x;
    int n0 = blockIdx.x * 8;
    __shared__ float s_emb[512];
    __shared__ float s_w[4096];  // 16 e-rows x 256 h
    for (int i = h; i < 512; i += 256) s_emb[i] = cOut[n0 * E_ + i];
    float acc[8];
#pragma unroll
    for (int r = 0; r < 8; r++) acc[r] = 0.f;
    for (int ch = 0; ch < 4; ch++) {
        __syncthreads();
        {
            const float4* src = (const float4*)(w1 + ch * 16 * H_);
            float4* dst = (float4*)s_w;
            for (int i = h; i < 1024; i += 256) dst[i] = src[i];
        }
        __syncthreads();
#pragma unroll
        for (int e = 0; e < 16; e++) {
            float w = s_w[e * H_ + h];
            int ge = ch * 16 + e;
#pragma unroll
            for (int r = 0; r < 8; r++) acc[r] += s_emb[r * 64 + ge] * w;
        }
    }
#pragma unroll
    for (int r = 0; r < 8; r++) g_T1c[(n0 + r) * H_ + h] = acc[r];
}

__global__ void __launch_bounds__(256) k_T1o(const float* __restrict__ w1) {
    int h = threadIdx.x;
    int b = blockIdx.y;
    int o0 = blockIdx.x * 8;
    __shared__ float s_emb[512];
    __shared__ float s_w[4096];
    for (int i = h; i < 512; i += 256) s_emb[i] = g_objOut[(b * O_ + o0) * E_ + i];
    float acc[8];
#pragma unroll
    for (int r = 0; r < 8; r++) acc[r] = 0.f;
    for (int ch = 0; ch < 4; ch++) {
        __syncthreads();
        {
            const float4* src = (const float4*)(w1 + ch * 16 * H_);
            float4* dst = (float4*)s_w;
            for (int i = h; i < 1024; i += 256) dst[i] = src[i];
        }
        __syncthreads();
#pragma unroll
        for (int e = 0; e < 16; e++) {
            float w = s_w[e * H_ + h];
            int ge = ch * 16 + e;
#pragma unroll
            for (int r = 0; r < 8; r++) acc[r] += s_emb[r * 64 + ge] * w;
        }
    }
#pragma unroll
    for (int r = 0; r < 8; r++) g_T1o[(b * O_ + o0 + r) * H_ + h] = acc[r];
}

__global__ void k_arg(const float* __restrict__ cOut, const int* __restrict__ args) {
    int i = blockIdx.x * 256 + threadIdx.x;
    if (i < B_ * L_ * E_) {
        int bt = i >> 6, e = i & 63;
        g_arg[i] = cOut[args[bt] * E_ + e];
    }
}

__global__ void __launch_bounds__(256) k_parg(const float* __restrict__ mw1,
                                              const float* __restrict__ mb1) {
    int bt = blockIdx.x;
    int h = threadIdx.x;
    __shared__ float s_a[64];
    if (h < 64) s_a[h] = g_arg[bt * E_ + h];
    __syncthreads();
    float p = mb1[h];
#pragma unroll
    for (int e = 0; e < 64; e++) p += s_a[e] * __ldg(&mw1[(64 + e) * H_ + h]);
    g_parg[bt * H_ + h] = p;
}

__global__ void __launch_bounds__(256) k_meta(
    const float* __restrict__ meta_init,
    const float* __restrict__ mw1, const float* __restrict__ mw2,
    const float* __restrict__ mb2, const int* __restrict__ ops) {
    extern __shared__ float dsm[];
    float* s_w1a = dsm;            // 64*256
    float* s_w2m = dsm + 16384;    // 256*64
    __shared__ float s_meta[64], s_h[256], s_part[256];
    int b = blockIdx.x;
    int tid = threadIdx.x;
    {
        const float4* w1_4 = (const float4*)mw1;
        float4* d1 = (float4*)s_w1a;
        for (int i = tid; i < 4096; i += 256) d1[i] = w1_4[i];
        const float4* w2_4 = (const float4*)mw2;
        float4* d2 = (float4*)s_w2m;
        for (int i = tid; i < 4096; i += 256) d2[i] = w2_4[i];
    }
    float r_mb2 = (tid < 64) ? mb2[tid] : 0.f;
    if (tid < 64) s_meta[tid] = meta_init[tid];
    __syncthreads();
    for (int t = 0; t < L_; t++) {
        float pre = g_parg[(b * L_ + t) * H_ + tid];
#pragma unroll
        for (int a = 0; a < 64; a++) pre += s_meta[a] * s_w1a[a * H_ + tid];
        s_h[tid] = fmaxf(pre, 0.f);
        __syncthreads();
        {
            int a = tid & 63;
            int base = (tid >> 6) * 64;
            float s = 0.f;
#pragma unroll
            for (int hh = 0; hh < 64; hh++)
                s += s_h[base + hh] * s_w2m[(base + hh) * A_ + a];
            s_part[tid] = s;
        }
        __syncthreads();
        if (tid < 64) {
            float nm = r_mb2 + s_part[tid] + s_part[64 + tid] +
                       s_part[128 + tid] + s_part[192 + tid];
            float nv = (ops[b * L_ + t] == 0) ? nm : s_meta[tid];
            s_meta[tid] = nv;
            g_meta[(b * L_ + t) * A_ + tid] = nv;
        }
        __syncthreads();
    }
}

__global__ void __launch_bounds__(256) k_u(const float* __restrict__ aw1,
                                           const float* __restrict__ ab1) {
    int bt = blockIdx.x;
    int tid = threadIdx.x;
    __shared__ float s_m[64];
    if (tid < 64) s_m[tid] = g_meta[bt * A_ + tid];
    __syncthreads();
    float uv = ab1[tid];
#pragma unroll
    for (int a = 0; a < 64; a++) uv += s_m[a] * __ldg(&aw1[(64 + a) * H_ + tid]);
    g_u[bt * H_ + tid] = uv;
}

__global__ void __launch_bounds__(256) k_proj(const float* __restrict__ cOut) {
    int b = blockIdx.y;
    int tid = threadIdx.x;
    int w = tid >> 5, lane = tid & 31;
    __shared__ float s_arg[768];
    __shared__ float s_p[8][16];
    for (int i = tid; i < 768; i += 256) s_arg[i] = g_arg[b * 768 + i];
    __syncthreads();
    int n = blockIdx.x * 8 + w;
    const float* row = (n < C_) ? cOut + (size_t)n * 64
                                : g_objOut + (size_t)(b * O_ + n - C_) * 64;
    float x0 = row[lane], x1 = row[lane + 32];
#pragma unroll
    for (int s = 0; s < 12; s++) {
        float p = x0 * s_arg[s * 64 + lane] + x1 * s_arg[s * 64 + 32 + lane];
#pragma unroll
        for (int o = 16; o > 0; o >>= 1) p += __shfl_xor_sync(0xffffffffu, p, o);
        if (lane == 0) s_p[w][s] = p * (1.0f / 64.0f);
    }
    __syncwarp();
    if (lane < 16) {
        float v = (lane < 12) ? s_p[w][lane] : ((lane == 12) ? 1.0f : 0.0f);
        g_proj[(size_t)(b * N_ + n) * 16 + lane] = v;
        if (lane < 12) atomicAdd(&g_psum[b * 16 + lane], v);
    }
}

__global__ void __launch_bounds__(64) k_tinsum(const float* __restrict__ cIn) {
    int b = blockIdx.y;
    int e = threadIdx.x;
    int n0 = blockIdx.x * 64;
    float s = 0.f;
    for (int r = 0; r < 64; r++) {
        int n = n0 + r;
        const float* row = (n < C_) ? cIn + (size_t)n * 64
                                    : g_objIn + (size_t)(b * O_ + n - C_) * 64;
        s += row[e];
    }
    atomicAdd(&g_tInsum[b * E_ + e], s);
}

// ---------------- big GEMM: D_t = Hrel_t^T @ [tIn | proj | 1] ----------------
__global__ void __launch_bounds__(256) k_D(const int* __restrict__ ops,
                                           const float* __restrict__ cIn) {
    int t = blockIdx.y, b = blockIdx.z;
    if (ops[b * L_ + t] != 2) return;
    int h = threadIdx.x;
    __shared__ __align__(16) float s_X[64 * 80];
    float uh = g_u[(b * L_ + t) * H_ + h];
    unsigned long long acc[40];
#pragma unroll
    for (int j = 0; j < 40; j++) acc[j] = 0ULL;
    int nbase = blockIdx.x * 192;
    for (int tile = 0; tile < 3; tile++) {
        int n0 = nbase + tile * 64;
        {
            float4* dst = (float4*)s_X;
            for (int i = h; i < 1024; i += 256) {
                int r = i >> 4, c = i & 15;
                int n = n0 + r;
                const float4* src = (n < C_)
                    ? (const float4*)cIn + (size_t)n * 16
                    : (const float4*)g_objIn + (size_t)(b * O_ + n - C_) * 16;
                dst[r * 20 + c] = src[c];
            }
            {
                int r = h >> 2, c = h & 3;
                dst[r * 20 + 16 + c] =
                    ((const float4*)g_proj)[(size_t)(b * N_ + n0 + r) * 4 + c];
            }
        }
        __syncthreads();
        // depth-2 prefetch of T1 rows (MLP=2 covers L2 latency)
        float t1a = (n0 < C_) ? g_T1c[n0 * H_ + h]
                              : g_T1o[(b * O_ + n0 - C_) * H_ + h];
        int n1 = n0 + 1;
        float t1b = (n1 < C_) ? g_T1c[n1 * H_ + h]
                              : g_T1o[(b * O_ + n1 - C_) * H_ + h];
        for (int nl = 0; nl < 64; nl++) {
            float hv = fmaxf(t1a + uh, 0.f);
            t1a = t1b;
            if (nl < 62) {
                int n = n0 + nl + 2;
                t1b = (n < C_) ? g_T1c[n * H_ + h]
                               : g_T1o[(b * O_ + n - C_) * H_ + h];
            }
            unsigned long long hv2 = pack2(hv);
            const ulonglong2* xr = (const ulonglong2*)(s_X + nl * 80);
#pragma unroll
            for (int j = 0; j < 20; j++) {
                ulonglong2 p = xr[j];
                asm("fma.rn.f32x2 %0, %1, %2, %0;" : "+l"(acc[2 * j]) : "l"(hv2), "l"(p.x));
                asm("fma.rn.f32x2 %0, %1, %2, %0;" : "+l"(acc[2 * j + 1]) : "l"(hv2), "l"(p.y));
            }
        }
        __syncthreads();
    }
    float* dp = g_D + ((size_t)(b * L_ + t) * H_ + h) * DCOLS;
#pragma unroll
    for (int j = 0; j < 40; j++) {
        asm volatile("red.global.add.v2.f32 [%0], {%1, %2};"
                     :: "l"(dp + 2 * j), "f"(lo2(acc[j])), "f"(hi2(acc[j])) : "memory");
    }
}

// ---------------- k_E: E_t = W2^T @ D_t  (64 x 80, stored transposed [c][e']) --
__global__ void __launch_bounds__(256) k_E(const int* __restrict__ ops,
                                           const float* __restrict__ w2) {
    int t = blockIdx.x, b = blockIdx.y;
    if (ops[b * L_ + t] != 2) return;
    int tid = threadIdx.x;
    int ep = tid & 63;   // e'
    int cq = tid >> 6;   // 0..3, each 20 cols
    __shared__ __align__(16) float s_D[64 * 80];   // [hh][c]
    __shared__ __align__(16) float s_w2[64 * 64];  // [hh][e']
    unsigned long long acc[10];
#pragma unroll
    for (int j = 0; j < 10; j++) acc[j] = 0ULL;
    size_t dbase = (size_t)(b * L_ + t) * H_ * DCOLS;
    for (int ch = 0; ch < 4; ch++) {
        __syncthreads();
        {
            const float4* src = (const float4*)(g_D + dbase + ch * 64 * DCOLS);
            float4* dst = (float4*)s_D;
            for (int i = tid; i < 1280; i += 256) dst[i] = src[i];
            const float4* wsrc = (const float4*)(w2 + ch * 64 * 64);
            float4* wdst = (float4*)s_w2;
            for (int i = tid; i < 1024; i += 256) wdst[i] = wsrc[i];
        }
        __syncthreads();
        const unsigned long long* D2 = (const unsigned long long*)s_D;
#pragma unroll 8
        for (int hh = 0; hh < 64; hh++) {
            unsigned long long w2v = pack2(s_w2[hh * 64 + ep]);
            const unsigned long long* drow = D2 + hh * 40 + cq * 10;
#pragma unroll
            for (int j = 0; j < 10; j++) {
                asm("fma.rn.f32x2 %0, %1, %2, %0;" : "+l"(acc[j]) : "l"(w2v), "l"(drow[j]));
            }
        }
    }
    // write transposed: g_E[bt][c][e']
    float* eb = g_E + (size_t)(b * L_ + t) * DCOLS * 64;
#pragma unroll
    for (int j = 0; j < 10; j++) {
        int c = cq * 20 + 2 * j;
        eb[c * 64 + ep] = lo2(acc[j]);
        eb[(c + 1) * 64 + ep] = hi2(acc[j]);
    }
}

// ---------------- tiny serial recurrence: Msum, attsum ------------------------
__global__ void __launch_bounds__(1024) k_rec(const int* __restrict__ ops,
                                              const float* __restrict__ b2,
                                              const float* __restrict__ att_init) {
    __shared__ __align__(16) float s_Ms[4096];   // [e][a]
    __shared__ __align__(16) float s_E[5120];    // [c][e']
    __shared__ float s_meta[768], s_tmp[1024];
    __shared__ float s_as[64], s_ai[64], s_tis[64], s_b2[64], s_ps[12];
    __shared__ int s_op[12];
    int b = blockIdx.x, tid = threadIdx.x;
    for (int i = tid; i < 4096; i += 1024) s_Ms[i] = 0.f;
    if (tid < 768) s_meta[tid] = g_meta[b * 768 + tid];
    if (tid < 64) {
        s_ai[tid] = att_init[tid];
        s_as[tid] = (float)N_ * att_init[tid];
        s_tis[tid] = g_tInsum[b * 64 + tid];
        s_b2[tid] = b2[tid];
    }
    if (tid < 12) { s_op[tid] = ops[b * L_ + tid]; s_ps[tid] = g_psum[b * 16 + tid]; }
    __syncthreads();
    const float invN = 1.0f / (float)N_;
    int a = tid & 63, eg = tid >> 6;   // eg 0..15, e' = eg*4 .. +3
    int e0 = eg * 4;
    for (int t = 0; t < L_; t++) {
        int op = s_op[t];
        if (op == 1) {
            if (tid < 64) s_as[tid] += s_ps[t] * s_meta[t * 64 + tid];
            __syncthreads();
        } else if (op == 2) {
            // load E_t
            const float* esrc = g_E + (size_t)(b * L_ + t) * 5120;
            for (int i = tid; i < 5120; i += 1024) s_E[i] = esrc[i];
            __syncthreads();
            float aiv = s_ai[a];
            unsigned long long ai2 = pack2(aiv);
            unsigned long long acc2[2];
            {  // E_S (col 76) x att_init[a]
                ulonglong2 es = *(const ulonglong2*)(s_E + 76 * 64 + e0);
                acc2[0] = 0ULL; acc2[1] = 0ULL;
                asm("fma.rn.f32x2 %0, %1, %2, %0;" : "+l"(acc2[0]) : "l"(es.x), "l"(ai2));
                asm("fma.rn.f32x2 %0, %1, %2, %0;" : "+l"(acc2[1]) : "l"(es.y), "l"(ai2));
            }
            for (int s = 0; s < t; s++)
                if (s_op[s] == 1) {
                    unsigned long long mv = pack2(s_meta[s * 64 + a]);
                    ulonglong2 er = *(const ulonglong2*)(s_E + (64 + s) * 64 + e0);
                    asm("fma.rn.f32x2 %0, %1, %2, %0;" : "+l"(acc2[0]) : "l"(er.x), "l"(mv));
                    asm("fma.rn.f32x2 %0, %1, %2, %0;" : "+l"(acc2[1]) : "l"(er.y), "l"(mv));
                }
            // E_K @ Msum_pre
#pragma unroll 8
            for (int e = 0; e < 64; e++) {
                unsigned long long ms = pack2(s_Ms[e * 64 + a]);
                ulonglong2 ek = *(const ulonglong2*)(s_E + e * 64 + e0);
                asm("fma.rn.f32x2 %0, %1, %2, %0;" : "+l"(acc2[0]) : "l"(ek.x), "l"(ms));
                asm("fma.rn.f32x2 %0, %1, %2, %0;" : "+l"(acc2[1]) : "l"(ek.y), "l"(ms));
            }
            float asv = s_as[a];
            float m[4] = {lo2(acc2[0]), hi2(acc2[0]), lo2(acc2[1]), hi2(acc2[1])};
            float part = 0.f;
#pragma unroll
            for (int j = 0; j < 4; j++) {
                m[j] = (m[j] + s_b2[e0 + j] * asv) * invN;
                part += s_tis[e0 + j] * m[j];
            }
            s_tmp[eg * 64 + a] = part;
            __syncthreads();  // all reads of s_Ms / s_as done
#pragma unroll
            for (int j = 0; j < 4; j++) s_Ms[(e0 + j) * 64 + a] += m[j];
            if (tid < 64) {
                float d = 0.f;
#pragma unroll
                for (int g = 0; g < 16; g++) d += s_tmp[g * 64 + tid];
                s_as[tid] += d;
            }
            __syncthreads();
        }
    }
    for (int i = tid; i < 4096; i += 1024) g_Msum[b * 4096 + i] = s_Ms[i];
}

// ---------------- final: reconstruct att rows, ol = mean(att^2), max ---------
__global__ void __launch_bounds__(128) k_final(const int* __restrict__ ops,
                                               const float* __restrict__ cIn,
                                               const float* __restrict__ att_init) {
    int b = blockIdx.y;
    int ag = threadIdx.x;           // 0..15 -> a = ag*4..+3
    int ny = threadIdx.y;           // 0..7
    int tid = ny * 16 + ag;
    __shared__ float s_Ms[4096], s_meta[768], s_ai[64];
    __shared__ float s_ti[8][64], s_pr[8][16];
    __shared__ int s_opf[12];
    for (int i = tid; i < 4096; i += 128) s_Ms[i] = g_Msum[b * 4096 + i];
    for (int i = tid; i < 768; i += 128) s_meta[i] = g_meta[b * 768 + i];
    if (tid < 64) s_ai[tid] = att_init[tid];
    if (tid < 12) s_opf[tid] = ops[b * L_ + tid];
    int n0 = blockIdx.x * 8;
    for (int i = tid; i < 512; i += 128) {
        int r = i >> 6, e = i & 63;
        int n = n0 + r;
        const float* row = (n < C_) ? cIn + (size_t)n * 64
                                    : g_objIn + (size_t)(b * O_ + n - C_) * 64;
        s_ti[r][e] = row[e];
    }
    {
        int r = tid >> 4, c = tid & 15;
        s_pr[r][c] = g_proj[(size_t)(b * N_ + n0 + r) * 16 + c];
    }
    __syncthreads();
    int n = n0 + ny;
    int a0 = ag * 4;
    float v0 = s_ai[a0], v1 = s_ai[a0 + 1], v2 = s_ai[a0 + 2], v3 = s_ai[a0 + 3];
#pragma unroll
    for (int s = 0; s < 12; s++)
        if (s_opf[s] == 1) {
            float pp = s_pr[ny][s];
            v0 += pp * s_meta[s * 64 + a0];
            v1 += pp * s_meta[s * 64 + a0 + 1];
            v2 += pp * s_meta[s * 64 + a0 + 2];
            v3 += pp * s_meta[s * 64 + a0 + 3];
        }
    const float4* Ms4 = (const float4*)s_Ms;
#pragma unroll
    for (int e = 0; e < 64; e++) {
        float ti = s_ti[ny][e];
        float4 m = Ms4[e * 16 + ag];
        v0 += ti * m.x; v1 += ti * m.y; v2 += ti * m.z; v3 += ti * m.w;
    }
    float sq = v0 * v0 + v1 * v1 + v2 * v2 + v3 * v3;
#pragma unroll
    for (int o = 8; o > 0; o >>= 1) sq += __shfl_xor_sync(0xffffffffu, sq, o);
    if (ag == 0) {
        float ol = sq * (1.0f / 64.0f);
        g_ol[b * N_ + n] = ol;
        atomicMax(&g_olmax[b], __float_as_int(ol));  // ol >= 0
    }
}

__global__ void __launch_bounds__(1024) k_soft(float* __restrict__ out) {
    int b = blockIdx.x;
    int tid = threadIdx.x;
    __shared__ float s_red[1024];
    float mx = __int_as_float(g_olmax[b]);
    float lsum = 0.f;
    for (int n = tid; n < N_; n += 1024) lsum += expf(g_ol[b * N_ + n] - mx);
    s_red[tid] = lsum;
    __syncthreads();
    for (int s = 512; s > 0; s >>= 1) {
        if (tid < s) s_red[tid] += s_red[tid + s];
        __syncthreads();
    }
    float lse = logf(s_red[0]) + mx;
    for (int n = tid; n < N_; n += 1024) out[b * N_ + n] = g_ol[b * N_ + n] - lse;
}

// ---------------- launch ------------------------------------------------------
extern "C" void kernel_launch(void* const* d_in, const int* in_sizes, int n_in,
                              void* d_out, int out_size) {
    const float* class_embIn   = (const float*)d_in[0];
    const float* class_embOut  = (const float*)d_in[1];
    const float* attr_embIn    = (const float*)d_in[2];
    const float* attr_embOut   = (const float*)d_in[3];
    const float* concept_embIn = (const float*)d_in[4];
    const float* concept_embOut= (const float*)d_in[5];
    const float* meta_init     = (const float*)d_in[6];
    const float* attention_init= (const float*)d_in[8];
    const float* axon_w1       = (const float*)d_in[9];
    const float* axon_b1       = (const float*)d_in[10];
    const float* axon_w2       = (const float*)d_in[11];
    const float* axon_b2       = (const float*)d_in[12];
    const float* meta_w1       = (const float*)d_in[13];
    const float* meta_b1       = (const float*)d_in[14];
    const float* meta_w2       = (const float*)d_in[15];
    const float* meta_b2       = (const float*)d_in[16];
    const int*   program_ops   = (const int*)d_in[17];
    const int*   program_args  = (const int*)d_in[18];
    const int*   gt_classes    = (const int*)d_in[19];
    const int*   gt_attributes = (const int*)d_in[20];
    float* out = (float*)d_out;

    cudaFuncSetAttribute(k_meta, cudaFuncAttributeMaxDynamicSharedMemorySize,
                         32768 * (int)sizeof(float));

    k_zero<<<(B_ * L_ * H_ * DCOLS / 4 + 255) / 256, 256>>>();
    k_obj<<<dim3(32, B_), dim3(64, 4)>>>(class_embIn, class_embOut, attr_embIn,
                                         attr_embOut, gt_classes, gt_attributes);
    k_T1c<<<C_ / 8, 256>>>(concept_embOut, axon_w1);
    k_T1o<<<dim3(O_ / 8, B_), 256>>>(axon_w1);
    k_arg<<<(B_ * L_ * E_ + 255) / 256, 256>>>(concept_embOut, program_args);
    k_parg<<<B_ * L_, 256>>>(meta_w1, meta_b1);
    k_meta<<<B_, 256, 32768 * sizeof(float)>>>(meta_init, meta_w1, meta_w2,
                                               meta_b2, program_ops);
    k_u<<<B_ * L_, 256>>>(axon_w1, axon_b1);
    k_proj<<<dim3(N_ / 8, B_), 256>>>(concept_embOut);
    k_tinsum<<<dim3(N_ / 64, B_), 64>>>(concept_embIn);
    k_D<<<dim3(N_ / 192, L_, B_), 256>>>(program_ops, concept_embIn);
    k_E<<<dim3(L_, B_), 256>>>(program_ops, axon_w2);
    k_rec<<<B_, 1024>>>(program_ops, axon_b2, attention_init);
    k_final<<<dim3(N_ / 8, B_), dim3(16, 8)>>>(program_ops, concept_embIn,
                                               attention_init);
    k_soft<<<B_, 1024>>>(out);
}